// round 3
// baseline (speedup 1.0000x reference)
#include <cuda_runtime.h>

#define Bq 128
#define Tq 512
#define DIN 256
#define DH 1024
#define DOUT 1024
#define STEP_ELEMS (Bq * DH)          /* 131072 */

// Scratch: XS holds the input projection, then S (pre-activations) in place.
__device__ float g_XS[(size_t)Tq * STEP_ELEMS];     // 256 MB
__device__ float g_P[128 * 128 * 128];              // 8 MB split-K partials
__device__ unsigned g_bar_count;                    // zero-init; self-resetting
__device__ unsigned g_bar_sense;                    // ping-pongs across replays

typedef unsigned long long ull;

__device__ __forceinline__ ull ffma2(ull a, ull b, ull c) {
    ull d; asm("fma.rn.f32x2 %0, %1, %2, %3;" : "=l"(d) : "l"(a), "l"(b), "l"(c)); return d;
}
__device__ __forceinline__ ull pack2(float x) {
    ull d; asm("mov.b64 %0, {%1, %1};" : "=l"(d) : "f"(x)); return d;
}
__device__ __forceinline__ float2 up2(ull v) {
    float2 f; asm("mov.b64 {%0, %1}, %2;" : "=f"(f.x), "=f"(f.y) : "l"(v)); return f;
}

// 8x(8 M x 8 N) micro-tile compute over one BK=8 smem chunk, f32x2 packed.
#define GEMM_COMPUTE()                                                         \
    _Pragma("unroll")                                                          \
    for (int kk = 0; kk < 8; kk++) {                                           \
        float4 a0 = *(const float4*)&As[kk][tym * 8];                          \
        float4 a1 = *(const float4*)&As[kk][tym * 8 + 4];                      \
        ulonglong2 b0 = *(const ulonglong2*)&Bs[kk][txn * 8];                  \
        ulonglong2 b1 = *(const ulonglong2*)&Bs[kk][txn * 8 + 4];              \
        ull am[8] = {pack2(a0.x), pack2(a0.y), pack2(a0.z), pack2(a0.w),       \
                     pack2(a1.x), pack2(a1.y), pack2(a1.z), pack2(a1.w)};      \
        ull bn[4] = {b0.x, b0.y, b1.x, b1.y};                                  \
        _Pragma("unroll")                                                      \
        for (int i = 0; i < 8; i++) {                                          \
            _Pragma("unroll")                                                  \
            for (int j = 0; j < 4; j++) acc[i][j] = ffma2(am[i], bn[j], acc[i][j]); \
        }                                                                      \
    }

// ---------------------------------------------------------------------------
// Kernel 0: zero the t=0 output block for every batch row.
// ---------------------------------------------------------------------------
__global__ void k_zero_first(float* __restrict__ out) {
    int b = blockIdx.x;
    float4* p = (float4*)(out + (size_t)b * (Tq + 1) * DOUT);
    p[threadIdx.x] = make_float4(0.f, 0.f, 0.f, 0.f);
}

// ---------------------------------------------------------------------------
// Kernel 1: XS[t][b][h] = sum_i seq[b][t][i]*Wx_w[h][i] + Wx_b[h] + Wh_b[h]
// grid = (8, 512): blockIdx.y = t (128 consecutive rows share one t).
// ---------------------------------------------------------------------------
__global__ void __launch_bounds__(256) k_xproj(
        const float* __restrict__ seq, const float* __restrict__ Wx_w,
        const float* __restrict__ Wx_b, const float* __restrict__ Wh_b) {
    __shared__ float As[8][128];
    __shared__ float Bs[8][128];
    const int tid = threadIdx.x;
    const int txn = tid & 15, tym = tid >> 4;
    const int t = blockIdx.y;
    const int n0 = blockIdx.x << 7;
    const int lrow = tid >> 1;
    const int lkq = (tid & 1) << 2;

    const float* Abase = seq + ((size_t)lrow * Tq + t) * DIN + lkq;
    const float* Bbase = Wx_w + (size_t)(n0 + lrow) * DIN + lkq;

    ull acc[8][4];
#pragma unroll
    for (int i = 0; i < 8; i++)
#pragma unroll
        for (int j = 0; j < 4; j++) acc[i][j] = 0ull;

    const int NK = DIN / 8;  // 32
    float4 av = *(const float4*)Abase;
    float4 bv = *(const float4*)Bbase;
    for (int kc = 0; kc < NK; kc++) {
        __syncthreads();
        As[lkq + 0][lrow] = av.x; As[lkq + 1][lrow] = av.y;
        As[lkq + 2][lrow] = av.z; As[lkq + 3][lrow] = av.w;
        Bs[lkq + 0][lrow] = bv.x; Bs[lkq + 1][lrow] = bv.y;
        Bs[lkq + 2][lrow] = bv.z; Bs[lkq + 3][lrow] = bv.w;
        float4 avn = av, bvn = bv;
        if (kc + 1 < NK) {
            avn = *(const float4*)(Abase + (kc + 1) * 8);
            bvn = *(const float4*)(Bbase + (kc + 1) * 8);
        }
        __syncthreads();
        GEMM_COMPUTE();
        av = avn; bv = bvn;
    }

    float4 ba0 = *(const float4*)&Wx_b[n0 + txn * 8];
    float4 ba1 = *(const float4*)&Wx_b[n0 + txn * 8 + 4];
    float4 bb0 = *(const float4*)&Wh_b[n0 + txn * 8];
    float4 bb1 = *(const float4*)&Wh_b[n0 + txn * 8 + 4];
    ba0.x += bb0.x; ba0.y += bb0.y; ba0.z += bb0.z; ba0.w += bb0.w;
    ba1.x += bb1.x; ba1.y += bb1.y; ba1.z += bb1.z; ba1.w += bb1.w;

    float* C = g_XS + (size_t)t * STEP_ELEMS;
#pragma unroll
    for (int i = 0; i < 8; i++) {
        int m = tym * 8 + i;
        float2 p0 = up2(acc[i][0]), p1 = up2(acc[i][1]);
        float2 p2 = up2(acc[i][2]), p3 = up2(acc[i][3]);
        float4 w0 = make_float4(p0.x + ba0.x, p0.y + ba0.y, p1.x + ba0.z, p1.y + ba0.w);
        float4 w1 = make_float4(p2.x + ba1.x, p2.y + ba1.y, p3.x + ba1.z, p3.y + ba1.w);
        *(float4*)&C[m * DH + n0 + txn * 8] = w0;
        *(float4*)&C[m * DH + n0 + txn * 8 + 4] = w1;
    }
}

// ---------------------------------------------------------------------------
// Persistent recurrence: for t=1..511, S[t] = tanh(S[t-1]) @ Wh^T + XS[t].
// 128 blocks = 8 N-tiles x 16 K-slices; deterministic reduce phase.
// ---------------------------------------------------------------------------
__device__ __forceinline__ void grid_sync(unsigned& sense, unsigned nb) {
    __threadfence();
    __syncthreads();
    sense ^= 1u;
    if (threadIdx.x == 0) {
        unsigned prev = atomicAdd(&g_bar_count, 1u);
        if (prev == nb - 1u) {
            atomicExch(&g_bar_count, 0u);
            __threadfence();
            atomicExch(&g_bar_sense, sense);
        } else {
            unsigned v;
            do {
                asm volatile("ld.acquire.gpu.b32 %0, [%1];" : "=r"(v) : "l"(&g_bar_sense));
            } while (v != sense);
        }
    }
    __syncthreads();
}

__global__ void __launch_bounds__(256, 1) k_recur(const float* __restrict__ Wh_w) {
    __shared__ float As[8][128];
    __shared__ float Bs[8][128];
    const int tid = threadIdx.x;
    const int txn = tid & 15, tym = tid >> 4;
    const int ns = blockIdx.x >> 4;     // 0..7  (N tile)
    const int ks = blockIdx.x & 15;     // 0..15 (K slice)
    const int n0 = ns << 7;
    const int kbase = ks << 6;          // 64-wide K slice
    const int lrow = tid >> 1;
    const int lkq = (tid & 1) << 2;
    const unsigned nb = gridDim.x;

    unsigned sense;
    asm volatile("ld.acquire.gpu.b32 %0, [%1];" : "=r"(sense) : "l"(&g_bar_sense));
    __syncthreads();

    const float* Bbase = Wh_w + (size_t)(n0 + lrow) * DH + kbase + lkq;
    float* Pmine = g_P + (size_t)blockIdx.x * 16384;
    const int gtid = blockIdx.x * 256 + tid;

    for (int t = 1; t < Tq; t++) {
        // ---- phase A: partial GEMM over this block's K slice ----
        const float* Abase = g_XS + (size_t)(t - 1) * STEP_ELEMS + lrow * DH + kbase + lkq;
        ull acc[8][4];
#pragma unroll
        for (int i = 0; i < 8; i++)
#pragma unroll
            for (int j = 0; j < 4; j++) acc[i][j] = 0ull;

        float4 av = *(const float4*)Abase;
        float4 bv = *(const float4*)Bbase;
#pragma unroll
        for (int kc = 0; kc < 8; kc++) {
            __syncthreads();
            As[lkq + 0][lrow] = tanhf(av.x); As[lkq + 1][lrow] = tanhf(av.y);
            As[lkq + 2][lrow] = tanhf(av.z); As[lkq + 3][lrow] = tanhf(av.w);
            Bs[lkq + 0][lrow] = bv.x; Bs[lkq + 1][lrow] = bv.y;
            Bs[lkq + 2][lrow] = bv.z; Bs[lkq + 3][lrow] = bv.w;
            float4 avn = av, bvn = bv;
            if (kc + 1 < 8) {
                avn = *(const float4*)(Abase + (kc + 1) * 8);
                bvn = *(const float4*)(Bbase + (kc + 1) * 8);
            }
            __syncthreads();
            GEMM_COMPUTE();
            av = avn; bv = bvn;
        }
#pragma unroll
        for (int i = 0; i < 8; i++) {
            int m = tym * 8 + i;
            float2 p0 = up2(acc[i][0]), p1 = up2(acc[i][1]);
            float2 p2 = up2(acc[i][2]), p3 = up2(acc[i][3]);
            *(float4*)&Pmine[m * 128 + txn * 8]     = make_float4(p0.x, p0.y, p1.x, p1.y);
            *(float4*)&Pmine[m * 128 + txn * 8 + 4] = make_float4(p2.x, p2.y, p3.x, p3.y);
        }
        grid_sync(sense, nb);

        // ---- phase B: deterministic reduce of 16 K-slice partials into S[t] ----
        float* S = g_XS + (size_t)t * STEP_ELEMS;
#pragma unroll
        for (int i = 0; i < 4; i++) {
            int e = gtid + i * 32768;
            int m = e >> 10;
            int n = e & 1023;
            int ens = n >> 7, enn = n & 127;
            float sum = S[e];
            const float* Pp = g_P + (size_t)ens * 262144 + m * 128 + enn;
#pragma unroll
            for (int q = 0; q < 16; q++) sum += Pp[q * 16384];
            S[e] = sum;
        }
        grid_sync(sense, nb);
    }
}

// ---------------------------------------------------------------------------
// Kernel 3: out[b][t+1][o] = sum_h S[t][b][h]*Wo_w[o][h] + Wo_b[o]
// grid = (8, 512): blockIdx.y = t.
// ---------------------------------------------------------------------------
__global__ void __launch_bounds__(256) k_out(
        const float* __restrict__ Wo_w, const float* __restrict__ Wo_b,
        float* __restrict__ out) {
    __shared__ float As[8][128];
    __shared__ float Bs[8][128];
    const int tid = threadIdx.x;
    const int txn = tid & 15, tym = tid >> 4;
    const int t = blockIdx.y;
    const int n0 = blockIdx.x << 7;
    const int lrow = tid >> 1;
    const int lkq = (tid & 1) << 2;

    const float* Abase = g_XS + (size_t)t * STEP_ELEMS + lrow * DH + lkq;
    const float* Bbase = Wo_w + (size_t)(n0 + lrow) * DH + lkq;

    ull acc[8][4];
#pragma unroll
    for (int i = 0; i < 8; i++)
#pragma unroll
        for (int j = 0; j < 4; j++) acc[i][j] = 0ull;

    const int NK = DH / 8;  // 128
    float4 av = *(const float4*)Abase;
    float4 bv = *(const float4*)Bbase;
    for (int kc = 0; kc < NK; kc++) {
        __syncthreads();
        As[lkq + 0][lrow] = av.x; As[lkq + 1][lrow] = av.y;
        As[lkq + 2][lrow] = av.z; As[lkq + 3][lrow] = av.w;
        Bs[lkq + 0][lrow] = bv.x; Bs[lkq + 1][lrow] = bv.y;
        Bs[lkq + 2][lrow] = bv.z; Bs[lkq + 3][lrow] = bv.w;
        float4 avn = av, bvn = bv;
        if (kc + 1 < NK) {
            avn = *(const float4*)(Abase + (kc + 1) * 8);
            bvn = *(const float4*)(Bbase + (kc + 1) * 8);
        }
        __syncthreads();
        GEMM_COMPUTE();
        av = avn; bv = bvn;
    }

    float4 bo0 = *(const float4*)&Wo_b[n0 + txn * 8];
    float4 bo1 = *(const float4*)&Wo_b[n0 + txn * 8 + 4];

#pragma unroll
    for (int i = 0; i < 8; i++) {
        int m = tym * 8 + i;  // batch index
        float* Crow = out + ((size_t)m * (Tq + 1) + t + 1) * DOUT;
        float2 p0 = up2(acc[i][0]), p1 = up2(acc[i][1]);
        float2 p2 = up2(acc[i][2]), p3 = up2(acc[i][3]);
        float4 w0 = make_float4(p0.x + bo0.x, p0.y + bo0.y, p1.x + bo0.z, p1.y + bo0.w);
        float4 w1 = make_float4(p2.x + bo1.x, p2.y + bo1.y, p3.x + bo1.z, p3.y + bo1.w);
        *(float4*)&Crow[n0 + txn * 8] = w0;
        *(float4*)&Crow[n0 + txn * 8 + 4] = w1;
    }
}

extern "C" void kernel_launch(void* const* d_in, const int* in_sizes, int n_in,
                              void* d_out, int out_size) {
    const float* seq  = (const float*)d_in[0];
    const float* Wh_w = (const float*)d_in[1];
    const float* Wh_b = (const float*)d_in[2];
    const float* Wx_w = (const float*)d_in[3];
    const float* Wx_b = (const float*)d_in[4];
    const float* Wo_w = (const float*)d_in[5];
    const float* Wo_b = (const float*)d_in[6];
    float* out = (float*)d_out;

    k_zero_first<<<Bq, 256>>>(out);
    dim3 gp(DH / 128, Tq);
    k_xproj<<<gp, 256>>>(seq, Wx_w, Wx_b, Wh_b);
    k_recur<<<128, 256>>>(Wh_w);
    dim3 go(DOUT / 128, Tq);
    k_out<<<go, 256>>>(Wo_w, Wo_b, out);
}

// round 8
// speedup vs baseline: 1.8508x; 1.8508x over previous
#include <cuda_runtime.h>
#include <cuda_bf16.h>
#include <cstdint>

#define Bq 128
#define Tq 512
#define DIN 256
#define DH 1024
#define DOUT 1024
#define STEP_ELEMS (Bq * DH)          /* 131072 */

// Scratch
__device__ float g_XS[(size_t)Tq * STEP_ELEMS];     // 256 MB: XS then S in place
__device__ float g_T[STEP_ELEMS];                   // tanh(S[t-1]) hot buffer
__device__ float g_P[128 * 128 * 128];              // 8 MB split-K partials
__device__ unsigned g_bar_count;
__device__ unsigned g_bar_sense;

// ===========================================================================
// Padded bf16 tile layout: [128 rows][PADK cols], stride 72 bf16 = 144 B.
// Bank pattern for frag loads (row stride 36 words): bank = (4*row8 + qc) -> conflict-free.
// ===========================================================================
#define PADK 72
#define TILE_B (128 * PADK * 2)       /* 18432 bytes per tile */
#define SMEM_DYN (4 * TILE_B)         /* Ah, Al, Bh, Bl = 73728 */

__device__ __forceinline__ uint32_t cvt2bf(float lo, float hi) {
    uint32_t r;
    asm("cvt.rn.satfinite.bf16x2.f32 %0, %1, %2;" : "=r"(r) : "f"(hi), "f"(lo));
    return r;
}

// fp32 [128 x 64] (row-major, leading dim ld) -> bf16 hi/lo padded tiles.
__device__ __forceinline__ void conv_tile(const float* __restrict__ src, size_t ld,
                                          char* th, char* tl, int tid) {
#pragma unroll
    for (int i = 0; i < 8; i++) {
        int f = i * 256 + tid;
        int row = f >> 4;
        int c4 = (f & 15) << 2;
        const float4 v = *(const float4*)(src + (size_t)row * ld + c4);
        uint32_t h01 = cvt2bf(v.x, v.y);
        uint32_t h23 = cvt2bf(v.z, v.w);
        float r0 = v.x - __uint_as_float(h01 << 16);
        float r1 = v.y - __uint_as_float(h01 & 0xFFFF0000u);
        float r2 = v.z - __uint_as_float(h23 << 16);
        float r3 = v.w - __uint_as_float(h23 & 0xFFFF0000u);
        uint32_t l01 = cvt2bf(r0, r1);
        uint32_t l23 = cvt2bf(r2, r3);
        int off = (row * PADK + c4) * 2;
        *(uint2*)(th + off) = make_uint2(h01, h23);
        *(uint2*)(tl + off) = make_uint2(l01, l23);
    }
}

__device__ __forceinline__ uint32_t lds32(const char* t, int row, int col) {
    return *(const uint32_t*)(t + (row * PADK + col) * 2);
}

__device__ __forceinline__ void mma16816(float d[4], const uint32_t a[4], const uint32_t b[2]) {
    asm volatile(
        "mma.sync.aligned.m16n8k16.row.col.f32.bf16.bf16.f32 "
        "{%0,%1,%2,%3}, {%4,%5,%6,%7}, {%8,%9}, {%0,%1,%2,%3};"
        : "+f"(d[0]), "+f"(d[1]), "+f"(d[2]), "+f"(d[3])
        : "r"(a[0]), "r"(a[1]), "r"(a[2]), "r"(a[3]), "r"(b[0]), "r"(b[1]));
}

// One K=64 chunk: warp computes 32(M) x 64(N) with 2-split bf16 (3 MMAs/product).
// acc[mi][n][4]: mi in {0,1} (16-row halves), n in 0..7 (8-col tiles).
__device__ __forceinline__ void mma_chunk(const char* Ah, const char* Al,
                                          const char* Bh, const char* Bl,
                                          int m0, int nw0, int qr, int qc2,
                                          float acc[2][8][4]) {
#pragma unroll
    for (int k16 = 0; k16 < 4; k16++) {
        const int k0 = k16 * 16;
        uint32_t ah[2][4], al[2][4];
#pragma unroll
        for (int mi = 0; mi < 2; mi++) {
            const int r = m0 + mi * 16 + qr;
            ah[mi][0] = lds32(Ah, r,     k0 + qc2);
            ah[mi][1] = lds32(Ah, r + 8, k0 + qc2);
            ah[mi][2] = lds32(Ah, r,     k0 + qc2 + 8);
            ah[mi][3] = lds32(Ah, r + 8, k0 + qc2 + 8);
            al[mi][0] = lds32(Al, r,     k0 + qc2);
            al[mi][1] = lds32(Al, r + 8, k0 + qc2);
            al[mi][2] = lds32(Al, r,     k0 + qc2 + 8);
            al[mi][3] = lds32(Al, r + 8, k0 + qc2 + 8);
        }
#pragma unroll
        for (int n = 0; n < 8; n++) {
            const int rn = nw0 + n * 8 + qr;
            uint32_t bh[2], bl[2];
            bh[0] = lds32(Bh, rn, k0 + qc2);
            bh[1] = lds32(Bh, rn, k0 + qc2 + 8);
            bl[0] = lds32(Bl, rn, k0 + qc2);
            bl[1] = lds32(Bl, rn, k0 + qc2 + 8);
#pragma unroll
            for (int mi = 0; mi < 2; mi++) {
                mma16816(acc[mi][n], ah[mi], bh);
                mma16816(acc[mi][n], ah[mi], bl);
                mma16816(acc[mi][n], al[mi], bh);
            }
        }
    }
}

// ===========================================================================
// Generic 128x128 block GEMM: C = A[128,K] * B[128,K]^T + bias, K = NC*64.
// ===========================================================================
template<int NC, bool TWOB>
__device__ __forceinline__ void blk_gemm(
        const float* __restrict__ A, size_t lda,
        const float* __restrict__ B, size_t ldb,
        float* __restrict__ C, size_t ldc,
        const float* __restrict__ b1, const float* __restrict__ b2, int n0) {
    extern __shared__ char sb[];
    char* Ah = sb;
    char* Al = sb + TILE_B;
    char* Bh = sb + 2 * TILE_B;
    char* Bl = sb + 3 * TILE_B;

    const int tid = threadIdx.x;
    const int w = tid >> 5, lane = tid & 31;
    const int m0 = (w & 3) * 32;
    const int nw0 = (w >> 2) * 64;
    const int qr = lane >> 2, qc2 = (lane & 3) * 2;

    float acc[2][8][4];
#pragma unroll
    for (int mi = 0; mi < 2; mi++)
#pragma unroll
        for (int n = 0; n < 8; n++)
#pragma unroll
            for (int j = 0; j < 4; j++) acc[mi][n][j] = 0.f;

    for (int c = 0; c < NC; c++) {
        __syncthreads();
        conv_tile(A + c * 64, lda, Ah, Al, tid);
        conv_tile(B + c * 64, ldb, Bh, Bl, tid);
        __syncthreads();
        mma_chunk(Ah, Al, Bh, Bl, m0, nw0, qr, qc2, acc);
    }

#pragma unroll
    for (int mi = 0; mi < 2; mi++) {
        const int r = m0 + mi * 16 + qr;
#pragma unroll
        for (int n = 0; n < 8; n++) {
            const int col = n0 + nw0 + n * 8 + qc2;
            float bv0 = b1[col], bv1 = b1[col + 1];
            if (TWOB) { bv0 += b2[col]; bv1 += b2[col + 1]; }
            *(float2*)(C + (size_t)r * ldc + col) =
                make_float2(acc[mi][n][0] + bv0, acc[mi][n][1] + bv1);
            *(float2*)(C + (size_t)(r + 8) * ldc + col) =
                make_float2(acc[mi][n][2] + bv0, acc[mi][n][3] + bv1);
        }
    }
}

// Kernel 1: XS[t] = seq_t @ Wx^T + Wx_b + Wh_b
__global__ void __launch_bounds__(256) k_xproj_mm(
        const float* __restrict__ seq, const float* __restrict__ Wx_w,
        const float* __restrict__ Wx_b, const float* __restrict__ Wh_b) {
    const int t = blockIdx.y, n0 = blockIdx.x << 7;
    blk_gemm<DIN / 64, true>(seq + (size_t)t * DIN, (size_t)Tq * DIN,
                             Wx_w + (size_t)n0 * DIN, DIN,
                             g_XS + (size_t)t * STEP_ELEMS, DH,
                             Wx_b, Wh_b, n0);
}

// Kernel 3: out[:, t+1, :] = S[t] @ Wo^T + Wo_b
__global__ void __launch_bounds__(256) k_out_mm(
        const float* __restrict__ Wo_w, const float* __restrict__ Wo_b,
        float* __restrict__ out) {
    const int t = blockIdx.y, n0 = blockIdx.x << 7;
    blk_gemm<DH / 64, false>(g_XS + (size_t)t * STEP_ELEMS, DH,
                             Wo_w + (size_t)n0 * DH, DH,
                             out + (size_t)(t + 1) * DOUT, (size_t)(Tq + 1) * DOUT,
                             Wo_b, Wo_b, n0);
}

// ===========================================================================
// Small helpers
// ===========================================================================
__global__ void k_zero_first(float* __restrict__ out) {
    int b = blockIdx.x;
    float4* p = (float4*)(out + (size_t)b * (Tq + 1) * DOUT);
    p[threadIdx.x] = make_float4(0.f, 0.f, 0.f, 0.f);
}

__global__ void k_tanh0() {
    int i = blockIdx.x * blockDim.x + threadIdx.x;
    float4 v = *(const float4*)&g_XS[(size_t)i * 4];
    float4 r = make_float4(tanhf(v.x), tanhf(v.y), tanhf(v.z), tanhf(v.w));
    *(float4*)&g_T[(size_t)i * 4] = r;
}

__device__ __forceinline__ void grid_sync(unsigned& sense, unsigned nb) {
    __threadfence();
    __syncthreads();
    sense ^= 1u;
    if (threadIdx.x == 0) {
        unsigned prev = atomicAdd(&g_bar_count, 1u);
        if (prev == nb - 1u) {
            atomicExch(&g_bar_count, 0u);
            __threadfence();
            atomicExch(&g_bar_sense, sense);
        } else {
            unsigned v;
            do {
                asm volatile("ld.acquire.gpu.b32 %0, [%1];" : "=r"(v) : "l"(&g_bar_sense));
            } while (v != sense);
        }
    }
    __syncthreads();
}

// ===========================================================================
// Persistent recurrence: S[t] = tanh(S[t-1]) @ Wh^T + XS[t].
// 128 blocks = 8 N-tiles x 16 K-slices (K=64 each); Wh slice resident in smem
// as bf16 hi/lo for all 512 steps; deterministic reduce + fused tanh.
// ===========================================================================
__global__ void __launch_bounds__(256, 1) k_recur(const float* __restrict__ Wh_w) {
    extern __shared__ char sb[];
    char* Ah = sb;
    char* Al = sb + TILE_B;
    char* Bh = sb + 2 * TILE_B;
    char* Bl = sb + 3 * TILE_B;

    const int tid = threadIdx.x;
    const int w = tid >> 5, lane = tid & 31;
    const int m0 = (w & 3) * 32;
    const int nw0 = (w >> 2) * 64;
    const int qr = lane >> 2, qc2 = (lane & 3) * 2;

    const int ns = blockIdx.x >> 4;     // N tile (0..7)
    const int ks = blockIdx.x & 15;     // K slice (0..15)
    const int n0 = ns << 7;
    const int kbase = ks << 6;
    const unsigned nb = gridDim.x;

    unsigned sense;
    asm volatile("ld.acquire.gpu.b32 %0, [%1];" : "=r"(sense) : "l"(&g_bar_sense));

    // Wh slice -> persistent bf16 hi/lo tiles (rows = n, cols = k slice).
    conv_tile(Wh_w + (size_t)n0 * DH + kbase, DH, Bh, Bl, tid);
    __syncthreads();

    float* Pmine = g_P + (size_t)blockIdx.x * 16384;
    const int gtid = blockIdx.x * 256 + tid;

    for (int t = 1; t < Tq; t++) {
        // ---- phase A: 128x128 partial over this block's K=64 slice ----
        conv_tile(g_T + kbase, DH, Ah, Al, tid);
        __syncthreads();

        float acc[2][8][4];
#pragma unroll
        for (int mi = 0; mi < 2; mi++)
#pragma unroll
            for (int n = 0; n < 8; n++)
#pragma unroll
                for (int j = 0; j < 4; j++) acc[mi][n][j] = 0.f;

        mma_chunk(Ah, Al, Bh, Bl, m0, nw0, qr, qc2, acc);

#pragma unroll
        for (int mi = 0; mi < 2; mi++) {
            const int r = m0 + mi * 16 + qr;
#pragma unroll
            for (int n = 0; n < 8; n++) {
                const int col = nw0 + n * 8 + qc2;
                *(float2*)&Pmine[r * 128 + col] =
                    make_float2(acc[mi][n][0], acc[mi][n][1]);
                *(float2*)&Pmine[(r + 8) * 128 + col] =
                    make_float2(acc[mi][n][2], acc[mi][n][3]);
            }
        }
        grid_sync(sense, nb);

        // ---- phase B: reduce 16 partials into S[t]; write tanh into g_T ----
        float* S = g_XS + (size_t)t * STEP_ELEMS;
#pragma unroll
        for (int i = 0; i < 4; i++) {
            int e = gtid + i * 32768;
            int n = e & 1023;
            int ens = n >> 7, enn = n & 127;
            int m = e >> 10;
            float sum = S[e];
            const float* Pp = g_P + (size_t)ens * 262144 + m * 128 + enn;
#pragma unroll
            for (int q = 0; q < 16; q++) sum += Pp[q * 16384];
            S[e] = sum;
            g_T[e] = tanhf(sum);
        }
        grid_sync(sense, nb);
    }
}

// ===========================================================================
extern "C" void kernel_launch(void* const* d_in, const int* in_sizes, int n_in,
                              void* d_out, int out_size) {
    const float* seq  = (const float*)d_in[0];
    const float* Wh_w = (const float*)d_in[1];
    const float* Wh_b = (const float*)d_in[2];
    const float* Wx_w = (const float*)d_in[3];
    const float* Wx_b = (const float*)d_in[4];
    const float* Wo_w = (const float*)d_in[5];
    const float* Wo_b = (const float*)d_in[6];
    float* out = (float*)d_out;

    cudaFuncSetAttribute(k_xproj_mm, cudaFuncAttributeMaxDynamicSharedMemorySize, SMEM_DYN);
    cudaFuncSetAttribute(k_out_mm,   cudaFuncAttributeMaxDynamicSharedMemorySize, SMEM_DYN);
    cudaFuncSetAttribute(k_recur,    cudaFuncAttributeMaxDynamicSharedMemorySize, SMEM_DYN);

    k_zero_first<<<Bq, 256>>>(out);
    dim3 gp(DH / 128, Tq);
    k_xproj_mm<<<gp, 256, SMEM_DYN>>>(seq, Wx_w, Wx_b, Wh_b);
    k_tanh0<<<128, 256>>>();
    k_recur<<<128, 256, SMEM_DYN>>>(Wh_w);
    dim3 go(DOUT / 128, Tq);
    k_out_mm<<<go, 256, SMEM_DYN>>>(Wo_w, Wo_b, out);
}

// round 9
// speedup vs baseline: 2.2513x; 1.2164x over previous
#include <cuda_runtime.h>
#include <cuda_bf16.h>
#include <cstdint>

#define Bq 128
#define Tq 512
#define DIN 256
#define DH 1024
#define DOUT 1024
#define STEP_ELEMS (Bq * DH)          /* 131072 */

// ---------------------------------------------------------------------------
// Global scratch
// ---------------------------------------------------------------------------
__device__ float g_XS[(size_t)Tq * STEP_ELEMS];          // 256 MB fp32 input proj
__device__ __nv_bfloat16 g_Sh[(size_t)Tq * STEP_ELEMS];  // 128 MB S hi split
__device__ __nv_bfloat16 g_Sl[(size_t)Tq * STEP_ELEMS];  // 128 MB S lo split
__device__ __nv_bfloat16 g_Th[STEP_ELEMS], g_Tl[STEP_ELEMS];   // tanh splits
__device__ __nv_bfloat16 g_Whh[DH * DH],  g_Whl[DH * DH];
__device__ __nv_bfloat16 g_Wxh[DH * DIN], g_Wxl[DH * DIN];
__device__ __nv_bfloat16 g_Woh[DOUT * DH], g_Wol[DOUT * DH];
__device__ float g_P[128 * 8192];                        // split-K partials (4 MB)
__device__ unsigned g_bar_count;
__device__ unsigned g_bar_sense;

__device__ __forceinline__ uint32_t cvt2bf(float lo, float hi) {
    uint32_t r;
    asm("cvt.rn.satfinite.bf16x2.f32 %0, %1, %2;" : "=r"(r) : "f"(hi), "f"(lo));
    return r;
}

// split a float4 into bf16 hi/lo arrays at element offset e
__device__ __forceinline__ void split4(float4 v, __nv_bfloat16* dh, __nv_bfloat16* dl, size_t e) {
    uint32_t h01 = cvt2bf(v.x, v.y), h23 = cvt2bf(v.z, v.w);
    float l0 = v.x - __uint_as_float(h01 << 16);
    float l1 = v.y - __uint_as_float(h01 & 0xFFFF0000u);
    float l2 = v.z - __uint_as_float(h23 << 16);
    float l3 = v.w - __uint_as_float(h23 & 0xFFFF0000u);
    *(uint2*)(dh + e) = make_uint2(h01, h23);
    *(uint2*)(dl + e) = make_uint2(cvt2bf(l0, l1), cvt2bf(l2, l3));
}

__device__ __forceinline__ void mma16816(float d[4], const uint32_t a[4], const uint32_t b[2]) {
    asm volatile(
        "mma.sync.aligned.m16n8k16.row.col.f32.bf16.bf16.f32 "
        "{%0,%1,%2,%3}, {%4,%5,%6,%7}, {%8,%9}, {%0,%1,%2,%3};"
        : "+f"(d[0]), "+f"(d[1]), "+f"(d[2]), "+f"(d[3])
        : "r"(a[0]), "r"(a[1]), "r"(a[2]), "r"(a[3]), "r"(b[0]), "r"(b[1]));
}

// word load from padded bf16 tile; WSTR = words per row (36 for PADK72, 68 for PW136)
template<int WSTR>
__device__ __forceinline__ uint32_t ldsw(const char* t, int row, int col) {
    return *(const uint32_t*)(t + row * (WSTR * 4) + col * 2);
}

// ===========================================================================
// PADK=72 tiles (64-wide K chunks) for xproj / out GEMMs
// ===========================================================================
#define PADK 72
#define TILE_B (128 * PADK * 2)       /* 18432 B */
#define SMEM72 (4 * TILE_B)           /* 73728 */

// fp32 [128 x 64] -> bf16 hi/lo padded tiles (xproj A only)
__device__ __forceinline__ void conv_tile(const float* __restrict__ src, size_t ld,
                                          char* th, char* tl, int tid) {
#pragma unroll
    for (int i = 0; i < 8; i++) {
        int f = i * 256 + tid;
        int row = f >> 4;
        int c4 = (f & 15) << 2;
        const float4 v = *(const float4*)(src + (size_t)row * ld + c4);
        uint32_t h01 = cvt2bf(v.x, v.y);
        uint32_t h23 = cvt2bf(v.z, v.w);
        float r0 = v.x - __uint_as_float(h01 << 16);
        float r1 = v.y - __uint_as_float(h01 & 0xFFFF0000u);
        float r2 = v.z - __uint_as_float(h23 << 16);
        float r3 = v.w - __uint_as_float(h23 & 0xFFFF0000u);
        int off = (row * PADK + c4) * 2;
        *(uint2*)(th + off) = make_uint2(h01, h23);
        *(uint2*)(tl + off) = make_uint2(cvt2bf(r0, r1), cvt2bf(r2, r3));
    }
}

// bf16 [128 x 64] (lead dim ld elems) -> padded tile, pure copy
__device__ __forceinline__ void copy64(const __nv_bfloat16* __restrict__ src, size_t ld,
                                       char* dst, int tid) {
#pragma unroll
    for (int i = 0; i < 4; i++) {
        int f = i * 256 + tid;
        int row = f >> 3, c = f & 7;
        *(uint4*)(dst + row * (PADK * 2) + c * 16) =
            *(const uint4*)(src + (size_t)row * ld + c * 8);
    }
}

// Warp-tile MMA over one K=64 chunk, PADK layout. 8 warps: 32(M) x 64(N) each.
__device__ __forceinline__ void mma_chunk72(const char* Ah, const char* Al,
                                            const char* Bh, const char* Bl,
                                            int m0, int nw0, int qr, int qc2,
                                            float acc[2][8][4]) {
#pragma unroll
    for (int k16 = 0; k16 < 4; k16++) {
        const int k0 = k16 * 16;
        uint32_t ah[2][4], al[2][4];
#pragma unroll
        for (int mi = 0; mi < 2; mi++) {
            const int r = m0 + mi * 16 + qr;
            ah[mi][0] = ldsw<36>(Ah, r,     k0 + qc2);
            ah[mi][1] = ldsw<36>(Ah, r + 8, k0 + qc2);
            ah[mi][2] = ldsw<36>(Ah, r,     k0 + qc2 + 8);
            ah[mi][3] = ldsw<36>(Ah, r + 8, k0 + qc2 + 8);
            al[mi][0] = ldsw<36>(Al, r,     k0 + qc2);
            al[mi][1] = ldsw<36>(Al, r + 8, k0 + qc2);
            al[mi][2] = ldsw<36>(Al, r,     k0 + qc2 + 8);
            al[mi][3] = ldsw<36>(Al, r + 8, k0 + qc2 + 8);
        }
#pragma unroll
        for (int n = 0; n < 8; n++) {
            const int rn = nw0 + n * 8 + qr;
            uint32_t bh[2], bl[2];
            bh[0] = ldsw<36>(Bh, rn, k0 + qc2);
            bh[1] = ldsw<36>(Bh, rn, k0 + qc2 + 8);
            bl[0] = ldsw<36>(Bl, rn, k0 + qc2);
            bl[1] = ldsw<36>(Bl, rn, k0 + qc2 + 8);
#pragma unroll
            for (int mi = 0; mi < 2; mi++) {
                mma16816(acc[mi][n], ah[mi], bh);
                mma16816(acc[mi][n], ah[mi], bl);
                mma16816(acc[mi][n], al[mi], bh);
            }
        }
    }
}

// ===========================================================================
// Pre-split all weights once (Wh, Wx, Wo) into bf16 hi/lo.
// ===========================================================================
#define NWH (DH * DH / 4)
#define NWX (DH * DIN / 4)
#define NWO (DOUT * DH / 4)
__global__ void k_split_all(const float* __restrict__ wh, const float* __restrict__ wx,
                            const float* __restrict__ wo) {
    int i = blockIdx.x * blockDim.x + threadIdx.x;
    if (i < NWH) {
        split4(((const float4*)wh)[i], g_Whh, g_Whl, (size_t)i * 4);
    } else if (i < NWH + NWX) {
        int j = i - NWH;
        split4(((const float4*)wx)[j], g_Wxh, g_Wxl, (size_t)j * 4);
    } else {
        int j = i - NWH - NWX;
        split4(((const float4*)wo)[j], g_Woh, g_Wol, (size_t)j * 4);
    }
}

// After xproj: S[0]=XS[0]; emit splits of S[0] and tanh(S[0]).
__global__ void k_init_step0() {
    int i = blockIdx.x * blockDim.x + threadIdx.x;   // 32768 threads, 1 float4 each
    float4 v = *(const float4*)&g_XS[(size_t)i * 4];
    split4(v, g_Sh, g_Sl, (size_t)i * 4);
    float4 th = make_float4(tanhf(v.x), tanhf(v.y), tanhf(v.z), tanhf(v.w));
    split4(th, g_Th, g_Tl, (size_t)i * 4);
}

__global__ void k_zero_first(float* __restrict__ out) {
    int b = blockIdx.x;
    float4* p = (float4*)(out + (size_t)b * (Tq + 1) * DOUT);
    p[threadIdx.x] = make_float4(0.f, 0.f, 0.f, 0.f);
}

// ===========================================================================
// Kernel 1: XS[t] = seq_t @ Wx^T + Wx_b + Wh_b   (A fp32-conv, B pre-split)
// ===========================================================================
__global__ void __launch_bounds__(256) k_xproj_mm(
        const float* __restrict__ seq,
        const float* __restrict__ Wx_b, const float* __restrict__ Wh_b) {
    extern __shared__ char sb[];
    char* Ah = sb;
    char* Al = sb + TILE_B;
    char* Bh = sb + 2 * TILE_B;
    char* Bl = sb + 3 * TILE_B;
    const int t = blockIdx.y, n0 = blockIdx.x << 7;
    const int tid = threadIdx.x;
    const int w = tid >> 5, lane = tid & 31;
    const int m0 = (w & 3) * 32, nw0 = (w >> 2) * 64;
    const int qr = lane >> 2, qc2 = (lane & 3) * 2;

    float acc[2][8][4] = {};
    const float* A = seq + (size_t)t * DIN;
#pragma unroll
    for (int c = 0; c < DIN / 64; c++) {
        __syncthreads();
        conv_tile(A + c * 64, (size_t)Tq * DIN, Ah, Al, tid);
        copy64(g_Wxh + (size_t)n0 * DIN + c * 64, DIN, Bh, tid);
        copy64(g_Wxl + (size_t)n0 * DIN + c * 64, DIN, Bl, tid);
        __syncthreads();
        mma_chunk72(Ah, Al, Bh, Bl, m0, nw0, qr, qc2, acc);
    }

    float* C = g_XS + (size_t)t * STEP_ELEMS;
#pragma unroll
    for (int mi = 0; mi < 2; mi++) {
        const int r = m0 + mi * 16 + qr;
#pragma unroll
        for (int n = 0; n < 8; n++) {
            const int col = n0 + nw0 + n * 8 + qc2;
            float bv0 = Wx_b[col] + Wh_b[col];
            float bv1 = Wx_b[col + 1] + Wh_b[col + 1];
            *(float2*)(C + (size_t)r * DH + col) =
                make_float2(acc[mi][n][0] + bv0, acc[mi][n][1] + bv1);
            *(float2*)(C + (size_t)(r + 8) * DH + col) =
                make_float2(acc[mi][n][2] + bv0, acc[mi][n][3] + bv1);
        }
    }
}

// ===========================================================================
// Kernel 3: out[:, t+1, :] = S[t] @ Wo^T + Wo_b   (all operands pre-split, copy-only)
// ===========================================================================
__global__ void __launch_bounds__(256) k_out_mm(
        const float* __restrict__ Wo_b, float* __restrict__ out) {
    extern __shared__ char sb[];
    char* Ah = sb;
    char* Al = sb + TILE_B;
    char* Bh = sb + 2 * TILE_B;
    char* Bl = sb + 3 * TILE_B;
    const int t = blockIdx.y, n0 = blockIdx.x << 7;
    const int tid = threadIdx.x;
    const int w = tid >> 5, lane = tid & 31;
    const int m0 = (w & 3) * 32, nw0 = (w >> 2) * 64;
    const int qr = lane >> 2, qc2 = (lane & 3) * 2;

    float acc[2][8][4] = {};
    const __nv_bfloat16* Shp = g_Sh + (size_t)t * STEP_ELEMS;
    const __nv_bfloat16* Slp = g_Sl + (size_t)t * STEP_ELEMS;
#pragma unroll 1
    for (int c = 0; c < DH / 64; c++) {
        __syncthreads();
        copy64(Shp + c * 64, DH, Ah, tid);
        copy64(Slp + c * 64, DH, Al, tid);
        copy64(g_Woh + (size_t)n0 * DH + c * 64, DH, Bh, tid);
        copy64(g_Wol + (size_t)n0 * DH + c * 64, DH, Bl, tid);
        __syncthreads();
        mma_chunk72(Ah, Al, Bh, Bl, m0, nw0, qr, qc2, acc);
    }

    float* C = out + (size_t)(t + 1) * DOUT;
    const size_t ldc = (size_t)(Tq + 1) * DOUT;
#pragma unroll
    for (int mi = 0; mi < 2; mi++) {
        const int r = m0 + mi * 16 + qr;
#pragma unroll
        for (int n = 0; n < 8; n++) {
            const int col = n0 + nw0 + n * 8 + qc2;
            float bv0 = Wo_b[col], bv1 = Wo_b[col + 1];
            *(float2*)(C + (size_t)r * ldc + col) =
                make_float2(acc[mi][n][0] + bv0, acc[mi][n][1] + bv1);
            *(float2*)(C + (size_t)(r + 8) * ldc + col) =
                make_float2(acc[mi][n][2] + bv0, acc[mi][n][3] + bv1);
        }
    }
}

// ===========================================================================
// Persistent recurrence. 128 blocks = 16 N-tiles (64 wide) x 8 K-slices (128 wide).
// 512 threads. Wh slice resident in smem. Reduce fuses tanh + both bf16 splits.
// ===========================================================================
#define PW 136
#define PWB (PW * 2)                   /* 272 B row stride */
#define SMEM_RC (2 * (128 * PWB) + 2 * (64 * PWB))   /* 104448 */

__device__ __forceinline__ void grid_sync(unsigned& sense, unsigned nb) {
    __threadfence();
    __syncthreads();
    sense ^= 1u;
    if (threadIdx.x == 0) {
        unsigned prev = atomicAdd(&g_bar_count, 1u);
        if (prev == nb - 1u) {
            atomicExch(&g_bar_count, 0u);
            __threadfence();
            atomicExch(&g_bar_sense, sense);
        } else {
            unsigned v;
            do {
                asm volatile("ld.acquire.gpu.b32 %0, [%1];" : "=r"(v) : "l"(&g_bar_sense));
            } while (v != sense);
        }
    }
    __syncthreads();
}

__global__ void __launch_bounds__(512, 1) k_recur() {
    extern __shared__ char sb[];
    char* Ah = sb;                          // 128 x 136 bf16 = 34816
    char* Al = sb + 34816;
    char* Bh = sb + 2 * 34816;              // 64 x 136 bf16 = 17408
    char* Bl = sb + 2 * 34816 + 17408;

    const int tid = threadIdx.x;
    const int w = tid >> 5, lane = tid & 31;
    const int m0 = (w & 7) * 16;            // 8 M-groups of 16
    const int nw0 = (w >> 3) * 32;          // 2 N-groups of 32
    const int qr = lane >> 2, qc2 = (lane & 3) * 2;

    const int ns = blockIdx.x >> 3;         // 0..15  N tile (64 wide)
    const int ks = blockIdx.x & 7;          // 0..7   K slice (128 wide)
    const int n0 = ns << 6;
    const int kbase = ks << 7;
    const unsigned nb = gridDim.x;

    unsigned sense;
    asm volatile("ld.acquire.gpu.b32 %0, [%1];" : "=r"(sense) : "l"(&g_bar_sense));

    // Resident Wh slice: rows n0..n0+63, cols kbase..kbase+127 (pure copy)
#pragma unroll
    for (int i = 0; i < 2; i++) {
        int f = i * 512 + tid;              // 1024 uint4 per tile
        int row = f >> 4, c = f & 15;
        *(uint4*)(Bh + row * PWB + c * 16) =
            *(const uint4*)(g_Whh + (size_t)(n0 + row) * DH + kbase + c * 8);
        *(uint4*)(Bl + row * PWB + c * 16) =
            *(const uint4*)(g_Whl + (size_t)(n0 + row) * DH + kbase + c * 8);
    }
    __syncthreads();

    float* Pmine = g_P + (size_t)blockIdx.x * 8192;
    const int gtid = blockIdx.x * 512 + tid;

    for (int t = 1; t < Tq; t++) {
        // ---- phase A: copy tanh splits into smem (no conversion) ----
#pragma unroll
        for (int i = 0; i < 4; i++) {
            int f = i * 512 + tid;          // 2048 uint4 per tile
            int row = f >> 4, c = f & 15;
            *(uint4*)(Ah + row * PWB + c * 16) =
                *(const uint4*)(g_Th + (size_t)row * DH + kbase + c * 8);
            *(uint4*)(Al + row * PWB + c * 16) =
                *(const uint4*)(g_Tl + (size_t)row * DH + kbase + c * 8);
        }
        __syncthreads();

        // ---- MMA: warp computes 16(M) x 32(N) over K=128 ----
        float acc[4][4] = {};
#pragma unroll
        for (int k16 = 0; k16 < 8; k16++) {
            const int k0 = k16 * 16;
            uint32_t ah[4], al[4];
            ah[0] = ldsw<68>(Ah, m0 + qr,     k0 + qc2);
            ah[1] = ldsw<68>(Ah, m0 + 8 + qr, k0 + qc2);
            ah[2] = ldsw<68>(Ah, m0 + qr,     k0 + qc2 + 8);
            ah[3] = ldsw<68>(Ah, m0 + 8 + qr, k0 + qc2 + 8);
            al[0] = ldsw<68>(Al, m0 + qr,     k0 + qc2);
            al[1] = ldsw<68>(Al, m0 + 8 + qr, k0 + qc2);
            al[2] = ldsw<68>(Al, m0 + qr,     k0 + qc2 + 8);
            al[3] = ldsw<68>(Al, m0 + 8 + qr, k0 + qc2 + 8);
#pragma unroll
            for (int n = 0; n < 4; n++) {
                const int rn = nw0 + n * 8 + qr;
                uint32_t bh[2], bl[2];
                bh[0] = ldsw<68>(Bh, rn, k0 + qc2);
                bh[1] = ldsw<68>(Bh, rn, k0 + qc2 + 8);
                bl[0] = ldsw<68>(Bl, rn, k0 + qc2);
                bl[1] = ldsw<68>(Bl, rn, k0 + qc2 + 8);
                mma16816(acc[n], ah, bh);
                mma16816(acc[n], ah, bl);
                mma16816(acc[n], al, bh);
            }
        }
        // partial: [128 rows][64 cols] fp32
#pragma unroll
        for (int n = 0; n < 4; n++) {
            const int col = nw0 + n * 8 + qc2;
            *(float2*)&Pmine[(m0 + qr) * 64 + col]     = make_float2(acc[n][0], acc[n][1]);
            *(float2*)&Pmine[(m0 + 8 + qr) * 64 + col] = make_float2(acc[n][2], acc[n][3]);
        }
        grid_sync(sense, nb);

        // ---- phase B: reduce 8 partials, fuse tanh + both bf16 splits ----
        {
            const int e = gtid * 2;         // adjacent element pair
            const int m = e >> 10, n = e & 1023;
            const int nsp = n >> 6;
            const float* Pp = g_P + (size_t)nsp * 8 * 8192 + m * 64 + (n & 63);
            float2 s = *(const float2*)&g_XS[(size_t)t * STEP_ELEMS + e];
#pragma unroll
            for (int q = 0; q < 8; q++) {
                float2 p = *(const float2*)&Pp[(size_t)q * 8192];
                s.x += p.x; s.y += p.y;
            }
            const size_t se = (size_t)t * STEP_ELEMS + e;
            uint32_t h01 = cvt2bf(s.x, s.y);
            float sl0 = s.x - __uint_as_float(h01 << 16);
            float sl1 = s.y - __uint_as_float(h01 & 0xFFFF0000u);
            *(uint32_t*)((char*)g_Sh + se * 2) = h01;
            *(uint32_t*)((char*)g_Sl + se * 2) = cvt2bf(sl0, sl1);
            float t0 = tanhf(s.x), t1 = tanhf(s.y);
            uint32_t th01 = cvt2bf(t0, t1);
            float tl0 = t0 - __uint_as_float(th01 << 16);
            float tl1 = t1 - __uint_as_float(th01 & 0xFFFF0000u);
            *(uint32_t*)((char*)g_Th + (size_t)e * 2) = th01;
            *(uint32_t*)((char*)g_Tl + (size_t)e * 2) = cvt2bf(tl0, tl1);
        }
        grid_sync(sense, nb);
    }
}

// ===========================================================================
extern "C" void kernel_launch(void* const* d_in, const int* in_sizes, int n_in,
                              void* d_out, int out_size) {
    const float* seq  = (const float*)d_in[0];
    const float* Wh_w = (const float*)d_in[1];
    const float* Wh_b = (const float*)d_in[2];
    const float* Wx_w = (const float*)d_in[3];
    const float* Wx_b = (const float*)d_in[4];
    const float* Wo_w = (const float*)d_in[5];
    const float* Wo_b = (const float*)d_in[6];
    float* out = (float*)d_out;

    cudaFuncSetAttribute(k_xproj_mm, cudaFuncAttributeMaxDynamicSharedMemorySize, SMEM72);
    cudaFuncSetAttribute(k_out_mm,   cudaFuncAttributeMaxDynamicSharedMemorySize, SMEM72);
    cudaFuncSetAttribute(k_recur,    cudaFuncAttributeMaxDynamicSharedMemorySize, SMEM_RC);

    k_split_all<<<(NWH + NWX + NWO) / 256, 256>>>(Wh_w, Wx_w, Wo_w);
    k_zero_first<<<Bq, 256>>>(out);
    dim3 gp(DH / 128, Tq);
    k_xproj_mm<<<gp, 256, SMEM72>>>(seq, Wx_b, Wh_b);
    k_init_step0<<<128, 256>>>();
    k_recur<<<128, 512, SMEM_RC>>>();
    dim3 go(DOUT / 128, Tq);
    k_out_mm<<<go, 256, SMEM72>>>(Wo_b, out);
}

// round 11
// speedup vs baseline: 2.7745x; 1.2324x over previous
#include <cuda_runtime.h>
#include <cuda_bf16.h>
#include <cstdint>

#define Bq 128
#define Tq 512
#define DIN 256
#define DH 1024
#define DOUT 1024
#define STEP_ELEMS (Bq * DH)          /* 131072 */

// ---------------------------------------------------------------------------
// Global scratch
// ---------------------------------------------------------------------------
__device__ float g_XS[(size_t)Tq * STEP_ELEMS];          // 256 MB fp32 input proj
__device__ __half g_Sf[(size_t)Tq * STEP_ELEMS];         // 128 MB S (fp16) for k_out
__device__ __nv_bfloat16 g_Th[2 * STEP_ELEMS], g_Tl[2 * STEP_ELEMS];  // tanh splits (double buf)
__device__ __nv_bfloat16 g_Whh[DH * DH],  g_Whl[DH * DH];
__device__ __nv_bfloat16 g_Wxh[DH * DIN], g_Wxl[DH * DIN];
__device__ __half g_Wof[DOUT * DH];
__device__ float g_P[2 * 128 * 8192];                    // split-K partials (double buf, 8 MB)
__device__ unsigned g_bar_count;
__device__ unsigned g_bar_sense;
__device__ unsigned g_fA[16];   // partials ready per N-group (8 arrivals/step)
__device__ unsigned g_fB[8];    // tanh K-slice ready per K-group (16 arrivals/step)
__device__ unsigned g_fC[8];    // phase-A copy done per K-group (16 arrivals/step)

__device__ __forceinline__ uint32_t cvt2bf(float lo, float hi) {
    uint32_t r;
    asm("cvt.rn.satfinite.bf16x2.f32 %0, %1, %2;" : "=r"(r) : "f"(hi), "f"(lo));
    return r;
}
__device__ __forceinline__ uint32_t cvt2h(float lo, float hi) {
    uint32_t r;
    asm("cvt.rn.f16x2.f32 %0, %1, %2;" : "=r"(r) : "f"(hi), "f"(lo));
    return r;
}

// split a float4 into bf16 hi/lo arrays at element offset e
__device__ __forceinline__ void split4(float4 v, __nv_bfloat16* dh, __nv_bfloat16* dl, size_t e) {
    uint32_t h01 = cvt2bf(v.x, v.y), h23 = cvt2bf(v.z, v.w);
    float l0 = v.x - __uint_as_float(h01 << 16);
    float l1 = v.y - __uint_as_float(h01 & 0xFFFF0000u);
    float l2 = v.z - __uint_as_float(h23 << 16);
    float l3 = v.w - __uint_as_float(h23 & 0xFFFF0000u);
    *(uint2*)(dh + e) = make_uint2(h01, h23);
    *(uint2*)(dl + e) = make_uint2(cvt2bf(l0, l1), cvt2bf(l2, l3));
}

__device__ __forceinline__ void mma16816(float d[4], const uint32_t a[4], const uint32_t b[2]) {
    asm volatile(
        "mma.sync.aligned.m16n8k16.row.col.f32.bf16.bf16.f32 "
        "{%0,%1,%2,%3}, {%4,%5,%6,%7}, {%8,%9}, {%0,%1,%2,%3};"
        : "+f"(d[0]), "+f"(d[1]), "+f"(d[2]), "+f"(d[3])
        : "r"(a[0]), "r"(a[1]), "r"(a[2]), "r"(a[3]), "r"(b[0]), "r"(b[1]));
}
__device__ __forceinline__ void mma16816h(float d[4], const uint32_t a[4], const uint32_t b[2]) {
    asm volatile(
        "mma.sync.aligned.m16n8k16.row.col.f32.f16.f16.f32 "
        "{%0,%1,%2,%3}, {%4,%5,%6,%7}, {%8,%9}, {%0,%1,%2,%3};"
        : "+f"(d[0]), "+f"(d[1]), "+f"(d[2]), "+f"(d[3])
        : "r"(a[0]), "r"(a[1]), "r"(a[2]), "r"(a[3]), "r"(b[0]), "r"(b[1]));
}

template<int WSTR>
__device__ __forceinline__ uint32_t ldsw(const char* t, int row, int col) {
    return *(const uint32_t*)(t + row * (WSTR * 4) + col * 2);
}

// flag helpers (gpu-scope release/acquire)
__device__ __forceinline__ unsigned ldacq(const unsigned* p) {
    unsigned v;
    asm volatile("ld.acquire.gpu.b32 %0, [%1];" : "=r"(v) : "l"(p) : "memory");
    return v;
}
__device__ __forceinline__ void redrel(unsigned* p) {
    asm volatile("red.release.gpu.add.u32 [%0], 1;" :: "l"(p) : "memory");
}
__device__ __forceinline__ void waitge(const unsigned* p, unsigned tgt) {
    while (ldacq(p) < tgt) {}
}

// ===========================================================================
// PADK=72 tiles (64-wide K chunks)
// ===========================================================================
#define PADK 72
#define TILE_B (128 * PADK * 2)       /* 18432 B */
#define SMEM72 (4 * TILE_B)           /* xproj: Ah,Al,Bh,Bl */
#define SMEM_OUT (2 * TILE_B)         /* out: Af,Bf */

// fp32 [128 x 64] -> bf16 hi/lo padded tiles
__device__ __forceinline__ void conv_tile(const float* __restrict__ src, size_t ld,
                                          char* th, char* tl, int tid) {
#pragma unroll
    for (int i = 0; i < 8; i++) {
        int f = i * 256 + tid;
        int row = f >> 4;
        int c4 = (f & 15) << 2;
        const float4 v = *(const float4*)(src + (size_t)row * ld + c4);
        uint32_t h01 = cvt2bf(v.x, v.y);
        uint32_t h23 = cvt2bf(v.z, v.w);
        float r0 = v.x - __uint_as_float(h01 << 16);
        float r1 = v.y - __uint_as_float(h01 & 0xFFFF0000u);
        float r2 = v.z - __uint_as_float(h23 << 16);
        float r3 = v.w - __uint_as_float(h23 & 0xFFFF0000u);
        int off = (row * PADK + c4) * 2;
        *(uint2*)(th + off) = make_uint2(h01, h23);
        *(uint2*)(tl + off) = make_uint2(cvt2bf(r0, r1), cvt2bf(r2, r3));
    }
}

// 16-bit [128 x 64] (lead dim ld elems) -> padded tile, pure copy
__device__ __forceinline__ void copy64(const __nv_bfloat16* __restrict__ src, size_t ld,
                                       char* dst, int tid) {
#pragma unroll
    for (int i = 0; i < 4; i++) {
        int f = i * 256 + tid;
        int row = f >> 3, c = f & 7;
        *(uint4*)(dst + row * (PADK * 2) + c * 16) =
            *(const uint4*)(src + (size_t)row * ld + c * 8);
    }
}

// 3-product bf16 warp-tile MMA over one K=64 chunk. 8 warps: 32(M) x 64(N).
__device__ __forceinline__ void mma_chunk72(const char* Ah, const char* Al,
                                            const char* Bh, const char* Bl,
                                            int m0, int nw0, int qr, int qc2,
                                            float acc[2][8][4]) {
#pragma unroll
    for (int k16 = 0; k16 < 4; k16++) {
        const int k0 = k16 * 16;
        uint32_t ah[2][4], al[2][4];
#pragma unroll
        for (int mi = 0; mi < 2; mi++) {
            const int r = m0 + mi * 16 + qr;
            ah[mi][0] = ldsw<36>(Ah, r,     k0 + qc2);
            ah[mi][1] = ldsw<36>(Ah, r + 8, k0 + qc2);
            ah[mi][2] = ldsw<36>(Ah, r,     k0 + qc2 + 8);
            ah[mi][3] = ldsw<36>(Ah, r + 8, k0 + qc2 + 8);
            al[mi][0] = ldsw<36>(Al, r,     k0 + qc2);
            al[mi][1] = ldsw<36>(Al, r + 8, k0 + qc2);
            al[mi][2] = ldsw<36>(Al, r,     k0 + qc2 + 8);
            al[mi][3] = ldsw<36>(Al, r + 8, k0 + qc2 + 8);
        }
#pragma unroll
        for (int n = 0; n < 8; n++) {
            const int rn = nw0 + n * 8 + qr;
            uint32_t bh[2], bl[2];
            bh[0] = ldsw<36>(Bh, rn, k0 + qc2);
            bh[1] = ldsw<36>(Bh, rn, k0 + qc2 + 8);
            bl[0] = ldsw<36>(Bl, rn, k0 + qc2);
            bl[1] = ldsw<36>(Bl, rn, k0 + qc2 + 8);
#pragma unroll
            for (int mi = 0; mi < 2; mi++) {
                mma16816(acc[mi][n], ah[mi], bh);
                mma16816(acc[mi][n], ah[mi], bl);
                mma16816(acc[mi][n], al[mi], bh);
            }
        }
    }
}

// single-product fp16 warp-tile MMA over one K=64 chunk.
__device__ __forceinline__ void mma_chunk72h(const char* Af, const char* Bf,
                                             int m0, int nw0, int qr, int qc2,
                                             float acc[2][8][4]) {
#pragma unroll
    for (int k16 = 0; k16 < 4; k16++) {
        const int k0 = k16 * 16;
        uint32_t a[2][4];
#pragma unroll
        for (int mi = 0; mi < 2; mi++) {
            const int r = m0 + mi * 16 + qr;
            a[mi][0] = ldsw<36>(Af, r,     k0 + qc2);
            a[mi][1] = ldsw<36>(Af, r + 8, k0 + qc2);
            a[mi][2] = ldsw<36>(Af, r,     k0 + qc2 + 8);
            a[mi][3] = ldsw<36>(Af, r + 8, k0 + qc2 + 8);
        }
#pragma unroll
        for (int n = 0; n < 8; n++) {
            const int rn = nw0 + n * 8 + qr;
            uint32_t b[2];
            b[0] = ldsw<36>(Bf, rn, k0 + qc2);
            b[1] = ldsw<36>(Bf, rn, k0 + qc2 + 8);
#pragma unroll
            for (int mi = 0; mi < 2; mi++) mma16816h(acc[mi][n], a[mi], b);
        }
    }
}

// ===========================================================================
// Weight prep: Wh, Wx -> bf16 hi/lo; Wo -> fp16.
// ===========================================================================
#define NWH (DH * DH / 4)
#define NWX (DH * DIN / 4)
#define NWO (DOUT * DH / 4)
__global__ void k_split_all(const float* __restrict__ wh, const float* __restrict__ wx,
                            const float* __restrict__ wo) {
    int i = blockIdx.x * blockDim.x + threadIdx.x;
    if (i < NWH) {
        split4(((const float4*)wh)[i], g_Whh, g_Whl, (size_t)i * 4);
    } else if (i < NWH + NWX) {
        int j = i - NWH;
        split4(((const float4*)wx)[j], g_Wxh, g_Wxl, (size_t)j * 4);
    } else {
        int j = i - NWH - NWX;
        float4 v = ((const float4*)wo)[j];
        *(uint2*)(g_Wof + (size_t)j * 4) = make_uint2(cvt2h(v.x, v.y), cvt2h(v.z, v.w));
    }
}

// After xproj: S[0]=XS[0]; emit fp16 S[0] and tanh splits into T buffer 0.
__global__ void k_init_step0() {
    int i = blockIdx.x * blockDim.x + threadIdx.x;
    float4 v = *(const float4*)&g_XS[(size_t)i * 4];
    *(uint2*)(g_Sf + (size_t)i * 4) = make_uint2(cvt2h(v.x, v.y), cvt2h(v.z, v.w));
    float4 th = make_float4(tanhf(v.x), tanhf(v.y), tanhf(v.z), tanhf(v.w));
    split4(th, g_Th, g_Tl, (size_t)i * 4);
}

__global__ void k_zero_first(float* __restrict__ out) {
    int b = blockIdx.x;
    float4* p = (float4*)(out + (size_t)b * (Tq + 1) * DOUT);
    p[threadIdx.x] = make_float4(0.f, 0.f, 0.f, 0.f);
}

// ===========================================================================
// Kernel 1: XS[t] = seq_t @ Wx^T + Wx_b + Wh_b   (bf16 3-product)
// ===========================================================================
__global__ void __launch_bounds__(256) k_xproj_mm(
        const float* __restrict__ seq,
        const float* __restrict__ Wx_b, const float* __restrict__ Wh_b) {
    extern __shared__ char sb[];
    char* Ah = sb;
    char* Al = sb + TILE_B;
    char* Bh = sb + 2 * TILE_B;
    char* Bl = sb + 3 * TILE_B;
    const int t = blockIdx.y, n0 = blockIdx.x << 7;
    const int tid = threadIdx.x;
    const int w = tid >> 5, lane = tid & 31;
    const int m0 = (w & 3) * 32, nw0 = (w >> 2) * 64;
    const int qr = lane >> 2, qc2 = (lane & 3) * 2;

    float acc[2][8][4] = {};
    const float* A = seq + (size_t)t * DIN;
#pragma unroll
    for (int c = 0; c < DIN / 64; c++) {
        __syncthreads();
        conv_tile(A + c * 64, (size_t)Tq * DIN, Ah, Al, tid);
        copy64(g_Wxh + (size_t)n0 * DIN + c * 64, DIN, Bh, tid);
        copy64(g_Wxl + (size_t)n0 * DIN + c * 64, DIN, Bl, tid);
        __syncthreads();
        mma_chunk72(Ah, Al, Bh, Bl, m0, nw0, qr, qc2, acc);
    }

    float* C = g_XS + (size_t)t * STEP_ELEMS;
#pragma unroll
    for (int mi = 0; mi < 2; mi++) {
        const int r = m0 + mi * 16 + qr;
#pragma unroll
        for (int n = 0; n < 8; n++) {
            const int col = n0 + nw0 + n * 8 + qc2;
            float bv0 = Wx_b[col] + Wh_b[col];
            float bv1 = Wx_b[col + 1] + Wh_b[col + 1];
            *(float2*)(C + (size_t)r * DH + col) =
                make_float2(acc[mi][n][0] + bv0, acc[mi][n][1] + bv1);
            *(float2*)(C + (size_t)(r + 8) * DH + col) =
                make_float2(acc[mi][n][2] + bv0, acc[mi][n][3] + bv1);
        }
    }
}

// ===========================================================================
// Kernel 3: out[:, t+1, :] = S[t] @ Wo^T + Wo_b   (fp16 single-product)
// ===========================================================================
__global__ void __launch_bounds__(256) k_out_mm(
        const float* __restrict__ Wo_b, float* __restrict__ out) {
    extern __shared__ char sb[];
    char* Af = sb;
    char* Bf = sb + TILE_B;
    const int t = blockIdx.y, n0 = blockIdx.x << 7;
    const int tid = threadIdx.x;
    const int w = tid >> 5, lane = tid & 31;
    const int m0 = (w & 3) * 32, nw0 = (w >> 2) * 64;
    const int qr = lane >> 2, qc2 = (lane & 3) * 2;

    float acc[2][8][4] = {};
    const __nv_bfloat16* Sp = (const __nv_bfloat16*)(g_Sf + (size_t)t * STEP_ELEMS);
    const __nv_bfloat16* Wp = (const __nv_bfloat16*)(g_Wof + (size_t)n0 * DH);
#pragma unroll 1
    for (int c = 0; c < DH / 64; c++) {
        __syncthreads();
        copy64(Sp + c * 64, DH, Af, tid);
        copy64(Wp + c * 64, DH, Bf, tid);
        __syncthreads();
        mma_chunk72h(Af, Bf, m0, nw0, qr, qc2, acc);
    }

    float* C = out + (size_t)(t + 1) * DOUT;
    const size_t ldc = (size_t)(Tq + 1) * DOUT;
#pragma unroll
    for (int mi = 0; mi < 2; mi++) {
        const int r = m0 + mi * 16 + qr;
#pragma unroll
        for (int n = 0; n < 8; n++) {
            const int col = n0 + nw0 + n * 8 + qc2;
            float bv0 = Wo_b[col], bv1 = Wo_b[col + 1];
            *(float2*)(C + (size_t)r * ldc + col) =
                make_float2(acc[mi][n][0] + bv0, acc[mi][n][1] + bv1);
            *(float2*)(C + (size_t)(r + 8) * ldc + col) =
                make_float2(acc[mi][n][2] + bv0, acc[mi][n][3] + bv1);
        }
    }
}

// ===========================================================================
// Persistent recurrence. 128 blocks = 16 N-tiles (64 wide) x 8 K-slices (128 wide).
// Group-local flag sync; double-buffered T and P; reduce fuses tanh + splits + fp16 S.
// ===========================================================================
#define PW 136
#define PWB (PW * 2)
#define SMEM_RC (2 * (128 * PWB) + 2 * (64 * PWB))   /* 104448 */

__device__ __forceinline__ void grid_sync(unsigned& sense, unsigned nb) {
    __threadfence();
    __syncthreads();
    sense ^= 1u;
    if (threadIdx.x == 0) {
        unsigned prev = atomicAdd(&g_bar_count, 1u);
        if (prev == nb - 1u) {
            atomicExch(&g_bar_count, 0u);
            __threadfence();
            atomicExch(&g_bar_sense, sense);
        } else {
            unsigned v;
            do {
                asm volatile("ld.acquire.gpu.b32 %0, [%1];" : "=r"(v) : "l"(&g_bar_sense));
            } while (v != sense);
        }
    }
    __syncthreads();
}

__global__ void __launch_bounds__(512, 1) k_recur() {
    extern __shared__ char sb[];
    char* Ah = sb;                          // 128 x 136 bf16 = 34816
    char* Al = sb + 34816;
    char* Bh = sb + 2 * 34816;              // 64 x 136 bf16 = 17408
    char* Bl = sb + 2 * 34816 + 17408;

    const int tid = threadIdx.x;
    const int w = tid >> 5, lane = tid & 31;
    const int m0 = (w & 7) * 16;
    const int nw0 = (w >> 3) * 32;
    const int qr = lane >> 2, qc2 = (lane & 3) * 2;

    const int ns = blockIdx.x >> 3;         // 0..15  N tile (64 wide)
    const int ks = blockIdx.x & 7;          // 0..7   K slice (128 wide)
    const int n0 = ns << 6;
    const int kbase = ks << 7;
    const unsigned nb = gridDim.x;

    unsigned sense;
    asm volatile("ld.acquire.gpu.b32 %0, [%1];" : "=r"(sense) : "l"(&g_bar_sense));

    // Reset flags (replay-safe), then one full barrier.
    if (blockIdx.x == 0 && tid == 0) {
#pragma unroll
        for (int i = 0; i < 16; i++) g_fA[i] = 0u;
#pragma unroll
        for (int i = 0; i < 8; i++) { g_fB[i] = 0u; g_fC[i] = 0u; }
    }

    // Resident Wh slice
#pragma unroll
    for (int i = 0; i < 2; i++) {
        int f = i * 512 + tid;
        int row = f >> 4, c = f & 15;
        *(uint4*)(Bh + row * PWB + c * 16) =
            *(const uint4*)(g_Whh + (size_t)(n0 + row) * DH + kbase + c * 8);
        *(uint4*)(Bl + row * PWB + c * 16) =
            *(const uint4*)(g_Whl + (size_t)(n0 + row) * DH + kbase + c * 8);
    }
    grid_sync(sense, nb);

    for (int t = 1; t < Tq; t++) {
        const unsigned tm1 = (unsigned)(t - 1);
        // wait: T-slice data ready (flagB[ks]) + P anti-dep (flagB[ns>>1])
        if (tid == 0) {
            waitge(&g_fB[ks], 16u * tm1);
            waitge(&g_fB[ns >> 1], 16u * tm1);
        }
        __syncthreads();

        // phase A: copy tanh splits (buffer (t-1)&1) into smem
        const __nv_bfloat16* Thp = g_Th + (size_t)((t - 1) & 1) * STEP_ELEMS;
        const __nv_bfloat16* Tlp = g_Tl + (size_t)((t - 1) & 1) * STEP_ELEMS;
#pragma unroll
        for (int i = 0; i < 4; i++) {
            int f = i * 512 + tid;
            int row = f >> 4, c = f & 15;
            *(uint4*)(Ah + row * PWB + c * 16) =
                *(const uint4*)(Thp + (size_t)row * DH + kbase + c * 8);
            *(uint4*)(Al + row * PWB + c * 16) =
                *(const uint4*)(Tlp + (size_t)row * DH + kbase + c * 8);
        }
        __syncthreads();
        if (tid == 0) redrel(&g_fC[ks]);    // done reading T slice

        // MMA: warp computes 16(M) x 32(N) over K=128
        float acc[4][4] = {};
#pragma unroll
        for (int k16 = 0; k16 < 8; k16++) {
            const int k0 = k16 * 16;
            uint32_t ah[4], al[4];
            ah[0] = ldsw<68>(Ah, m0 + qr,     k0 + qc2);
            ah[1] = ldsw<68>(Ah, m0 + 8 + qr, k0 + qc2);
            ah[2] = ldsw<68>(Ah, m0 + qr,     k0 + qc2 + 8);
            ah[3] = ldsw<68>(Ah, m0 + 8 + qr, k0 + qc2 + 8);
            al[0] = ldsw<68>(Al, m0 + qr,     k0 + qc2);
            al[1] = ldsw<68>(Al, m0 + 8 + qr, k0 + qc2);
            al[2] = ldsw<68>(Al, m0 + qr,     k0 + qc2 + 8);
            al[3] = ldsw<68>(Al, m0 + 8 + qr, k0 + qc2 + 8);
#pragma unroll
            for (int n = 0; n < 4; n++) {
                const int rn = nw0 + n * 8 + qr;
                uint32_t bh[2], bl[2];
                bh[0] = ldsw<68>(Bh, rn, k0 + qc2);
                bh[1] = ldsw<68>(Bh, rn, k0 + qc2 + 8);
                bl[0] = ldsw<68>(Bl, rn, k0 + qc2);
                bl[1] = ldsw<68>(Bl, rn, k0 + qc2 + 8);
                mma16816(acc[n], ah, bh);
                mma16816(acc[n], ah, bl);
                mma16816(acc[n], al, bh);
            }
        }
        // write partial [128 rows x 64 cols] fp32 to P buffer t&1
        float* Pmine = g_P + (size_t)(t & 1) * 128 * 8192 + (size_t)blockIdx.x * 8192;
#pragma unroll
        for (int n = 0; n < 4; n++) {
            const int col = nw0 + n * 8 + qc2;
            *(float2*)&Pmine[(m0 + qr) * 64 + col]     = make_float2(acc[n][0], acc[n][1]);
            *(float2*)&Pmine[(m0 + 8 + qr) * 64 + col] = make_float2(acc[n][2], acc[n][3]);
        }
        __syncthreads();
        if (tid == 0) {
            redrel(&g_fA[ns]);
            // wait producers of our reduce patch + all readers of T buffer t&1
            waitge(&g_fA[2 * ks],     8u * (unsigned)t);
            waitge(&g_fA[2 * ks + 1], 8u * (unsigned)t);
            waitge(&g_fC[ks], 16u * tm1);
        }
        __syncthreads();

        // reduce: rows [8ns, 8ns+8), cols [128ks, 128ks+128); fuse tanh + splits + fp16 S
        {
            const int m = 8 * ns + (tid >> 6);
            const int c = 128 * ks + (tid & 63) * 2;
            const float* Pbase = g_P + (size_t)(t & 1) * 128 * 8192;
            float2 s = *(const float2*)&g_XS[(size_t)t * STEP_ELEMS + m * DH + c];
            const float* Pp = Pbase + (size_t)((2 * ks + ((tid & 63) >> 5)) * 8) * 8192
                              + m * 64 + (c & 63);
#pragma unroll
            for (int q = 0; q < 8; q++) {
                float2 p = *(const float2*)&Pp[(size_t)q * 8192];
                s.x += p.x; s.y += p.y;
            }
            const size_t se = (size_t)t * STEP_ELEMS + m * DH + c;
            *(uint32_t*)((char*)g_Sf + se * 2) = cvt2h(s.x, s.y);
            float t0 = tanhf(s.x), t1 = tanhf(s.y);
            uint32_t th01 = cvt2bf(t0, t1);
            float tl0 = t0 - __uint_as_float(th01 << 16);
            float tl1 = t1 - __uint_as_float(th01 & 0xFFFF0000u);
            const size_t te = (size_t)(t & 1) * STEP_ELEMS + m * DH + c;
            *(uint32_t*)((char*)g_Th + te * 2) = th01;
            *(uint32_t*)((char*)g_Tl + te * 2) = cvt2bf(tl0, tl1);
        }
        __syncthreads();
        if (tid == 0) redrel(&g_fB[ks]);
    }
}

// ===========================================================================
extern "C" void kernel_launch(void* const* d_in, const int* in_sizes, int n_in,
                              void* d_out, int out_size) {
    const float* seq  = (const float*)d_in[0];
    const float* Wh_w = (const float*)d_in[1];
    const float* Wh_b = (const float*)d_in[2];
    const float* Wx_w = (const float*)d_in[3];
    const float* Wx_b = (const float*)d_in[4];
    const float* Wo_w = (const float*)d_in[5];
    const float* Wo_b = (const float*)d_in[6];
    float* out = (float*)d_out;

    cudaFuncSetAttribute(k_xproj_mm, cudaFuncAttributeMaxDynamicSharedMemorySize, SMEM72);
    cudaFuncSetAttribute(k_out_mm,   cudaFuncAttributeMaxDynamicSharedMemorySize, SMEM_OUT);
    cudaFuncSetAttribute(k_recur,    cudaFuncAttributeMaxDynamicSharedMemorySize, SMEM_RC);

    k_split_all<<<(NWH + NWX + NWO) / 256, 256>>>(Wh_w, Wx_w, Wo_w);
    k_zero_first<<<Bq, 256>>>(out);
    dim3 gp(DH / 128, Tq);
    k_xproj_mm<<<gp, 256, SMEM72>>>(seq, Wx_b, Wh_b);
    k_init_step0<<<128, 256>>>();
    k_recur<<<128, 512, SMEM_RC>>>();
    dim3 go(DOUT / 128, Tq);
    k_out_mm<<<go, 256, SMEM_OUT>>>(Wo_b, out);
}

// round 17
// speedup vs baseline: 3.0771x; 1.1091x over previous
#include <cuda_runtime.h>
#include <cuda_bf16.h>
#include <cstdint>

#define Bq 128
#define Tq 512
#define DIN 256
#define DH 1024
#define DOUT 1024
#define STEP_ELEMS (Bq * DH)          /* 131072 */

// ---------------------------------------------------------------------------
// Global scratch
// ---------------------------------------------------------------------------
__device__ float g_XS[(size_t)Tq * STEP_ELEMS];          // 256 MB fp32 input proj
__device__ __half g_Sf[(size_t)Tq * STEP_ELEMS];         // 128 MB S (fp16) for k_out
__device__ __nv_bfloat16 g_Th[2 * STEP_ELEMS], g_Tl[2 * STEP_ELEMS];  // tanh splits (double buf)
__device__ __nv_bfloat16 g_Whh[DH * DH],  g_Whl[DH * DH];
__device__ __nv_bfloat16 g_Wxh[DH * DIN], g_Wxl[DH * DIN];
__device__ __half g_Wof[DOUT * DH];
__device__ float g_P[2 * 128 * 8192];                    // split-K partials (double buf)
__device__ unsigned g_bar_count;
__device__ unsigned g_bar_sense;
__device__ unsigned g_fA[16];   // partials ready per N-group (8 arrivals/step)
__device__ unsigned g_fB[8];    // tanh K-slice ready per K-group (16 arrivals/step)
__device__ unsigned g_fC[8];    // phase-A copy done per K-group (16 arrivals/step)

__device__ __forceinline__ uint32_t cvt2bf(float lo, float hi) {
    uint32_t r;
    asm("cvt.rn.satfinite.bf16x2.f32 %0, %1, %2;" : "=r"(r) : "f"(hi), "f"(lo));
    return r;
}
__device__ __forceinline__ uint32_t cvt2h(float lo, float hi) {
    uint32_t r;
    asm("cvt.rn.f16x2.f32 %0, %1, %2;" : "=r"(r) : "f"(hi), "f"(lo));
    return r;
}

__device__ __forceinline__ void split4(float4 v, __nv_bfloat16* dh, __nv_bfloat16* dl, size_t e) {
    uint32_t h01 = cvt2bf(v.x, v.y), h23 = cvt2bf(v.z, v.w);
    float l0 = v.x - __uint_as_float(h01 << 16);
    float l1 = v.y - __uint_as_float(h01 & 0xFFFF0000u);
    float l2 = v.z - __uint_as_float(h23 << 16);
    float l3 = v.w - __uint_as_float(h23 & 0xFFFF0000u);
    *(uint2*)(dh + e) = make_uint2(h01, h23);
    *(uint2*)(dl + e) = make_uint2(cvt2bf(l0, l1), cvt2bf(l2, l3));
}

__device__ __forceinline__ void mma16816(float d[4], const uint32_t a[4], const uint32_t b[2]) {
    asm volatile(
        "mma.sync.aligned.m16n8k16.row.col.f32.bf16.bf16.f32 "
        "{%0,%1,%2,%3}, {%4,%5,%6,%7}, {%8,%9}, {%0,%1,%2,%3};"
        : "+f"(d[0]), "+f"(d[1]), "+f"(d[2]), "+f"(d[3])
        : "r"(a[0]), "r"(a[1]), "r"(a[2]), "r"(a[3]), "r"(b[0]), "r"(b[1]));
}
__device__ __forceinline__ void mma16816h(float d[4], const uint32_t a[4], const uint32_t b[2]) {
    asm volatile(
        "mma.sync.aligned.m16n8k16.row.col.f32.f16.f16.f32 "
        "{%0,%1,%2,%3}, {%4,%5,%6,%7}, {%8,%9}, {%0,%1,%2,%3};"
        : "+f"(d[0]), "+f"(d[1]), "+f"(d[2]), "+f"(d[3])
        : "r"(a[0]), "r"(a[1]), "r"(a[2]), "r"(a[3]), "r"(b[0]), "r"(b[1]));
}

template<int WSTR>
__device__ __forceinline__ uint32_t ldsw(const char* t, int row, int col) {
    return *(const uint32_t*)(t + row * (WSTR * 4) + col * 2);
}

// flag helpers (gpu-scope release/acquire)
__device__ __forceinline__ unsigned ldacq(const unsigned* p) {
    unsigned v;
    asm volatile("ld.acquire.gpu.b32 %0, [%1];" : "=r"(v) : "l"(p) : "memory");
    return v;
}
__device__ __forceinline__ void redrel(unsigned* p) {
    asm volatile("red.release.gpu.add.u32 [%0], 1;" :: "l"(p) : "memory");
}
__device__ __forceinline__ void waitge(const unsigned* p, unsigned tgt) {
    while (ldacq(p) < tgt) {}
}

// ===========================================================================
// PADK=72 tiles (64-wide K chunks)
// ===========================================================================
#define PADK 72
#define TILE_B (128 * PADK * 2)       /* 18432 B */
#define SMEM72 (4 * TILE_B)
#define SMEM_OUT (2 * TILE_B)

__device__ __forceinline__ void conv_tile(const float* __restrict__ src, size_t ld,
                                          char* th, char* tl, int tid) {
#pragma unroll
    for (int i = 0; i < 8; i++) {
        int f = i * 256 + tid;
        int row = f >> 4;
        int c4 = (f & 15) << 2;
        const float4 v = *(const float4*)(src + (size_t)row * ld + c4);
        uint32_t h01 = cvt2bf(v.x, v.y);
        uint32_t h23 = cvt2bf(v.z, v.w);
        float r0 = v.x - __uint_as_float(h01 << 16);
        float r1 = v.y - __uint_as_float(h01 & 0xFFFF0000u);
        float r2 = v.z - __uint_as_float(h23 << 16);
        float r3 = v.w - __uint_as_float(h23 & 0xFFFF0000u);
        int off = (row * PADK + c4) * 2;
        *(uint2*)(th + off) = make_uint2(h01, h23);
        *(uint2*)(tl + off) = make_uint2(cvt2bf(r0, r1), cvt2bf(r2, r3));
    }
}

__device__ __forceinline__ void copy64(const __nv_bfloat16* __restrict__ src, size_t ld,
                                       char* dst, int tid) {
#pragma unroll
    for (int i = 0; i < 4; i++) {
        int f = i * 256 + tid;
        int row = f >> 3, c = f & 7;
        *(uint4*)(dst + row * (PADK * 2) + c * 16) =
            *(const uint4*)(src + (size_t)row * ld + c * 8);
    }
}

__device__ __forceinline__ void mma_chunk72(const char* Ah, const char* Al,
                                            const char* Bh, const char* Bl,
                                            int m0, int nw0, int qr, int qc2,
                                            float acc[2][8][4]) {
#pragma unroll
    for (int k16 = 0; k16 < 4; k16++) {
        const int k0 = k16 * 16;
        uint32_t ah[2][4], al[2][4];
#pragma unroll
        for (int mi = 0; mi < 2; mi++) {
            const int r = m0 + mi * 16 + qr;
            ah[mi][0] = ldsw<36>(Ah, r,     k0 + qc2);
            ah[mi][1] = ldsw<36>(Ah, r + 8, k0 + qc2);
            ah[mi][2] = ldsw<36>(Ah, r,     k0 + qc2 + 8);
            ah[mi][3] = ldsw<36>(Ah, r + 8, k0 + qc2 + 8);
            al[mi][0] = ldsw<36>(Al, r,     k0 + qc2);
            al[mi][1] = ldsw<36>(Al, r + 8, k0 + qc2);
            al[mi][2] = ldsw<36>(Al, r,     k0 + qc2 + 8);
            al[mi][3] = ldsw<36>(Al, r + 8, k0 + qc2 + 8);
        }
#pragma unroll
        for (int n = 0; n < 8; n++) {
            const int rn = nw0 + n * 8 + qr;
            uint32_t bh[2], bl[2];
            bh[0] = ldsw<36>(Bh, rn, k0 + qc2);
            bh[1] = ldsw<36>(Bh, rn, k0 + qc2 + 8);
            bl[0] = ldsw<36>(Bl, rn, k0 + qc2);
            bl[1] = ldsw<36>(Bl, rn, k0 + qc2 + 8);
#pragma unroll
            for (int mi = 0; mi < 2; mi++) {
                mma16816(acc[mi][n], ah[mi], bh);
                mma16816(acc[mi][n], ah[mi], bl);
                mma16816(acc[mi][n], al[mi], bh);
            }
        }
    }
}

__device__ __forceinline__ void mma_chunk72h(const char* Af, const char* Bf,
                                             int m0, int nw0, int qr, int qc2,
                                             float acc[2][8][4]) {
#pragma unroll
    for (int k16 = 0; k16 < 4; k16++) {
        const int k0 = k16 * 16;
        uint32_t a[2][4];
#pragma unroll
        for (int mi = 0; mi < 2; mi++) {
            const int r = m0 + mi * 16 + qr;
            a[mi][0] = ldsw<36>(Af, r,     k0 + qc2);
            a[mi][1] = ldsw<36>(Af, r + 8, k0 + qc2);
            a[mi][2] = ldsw<36>(Af, r,     k0 + qc2 + 8);
            a[mi][3] = ldsw<36>(Af, r + 8, k0 + qc2 + 8);
        }
#pragma unroll
        for (int n = 0; n < 8; n++) {
            const int rn = nw0 + n * 8 + qr;
            uint32_t b[2];
            b[0] = ldsw<36>(Bf, rn, k0 + qc2);
            b[1] = ldsw<36>(Bf, rn, k0 + qc2 + 8);
#pragma unroll
            for (int mi = 0; mi < 2; mi++) mma16816h(acc[mi][n], a[mi], b);
        }
    }
}

// ===========================================================================
// Weight prep: Wh, Wx -> bf16 hi/lo; Wo -> fp16.
// ===========================================================================
#define NWH (DH * DH / 4)
#define NWX (DH * DIN / 4)
#define NWO (DOUT * DH / 4)
__global__ void k_split_all(const float* __restrict__ wh, const float* __restrict__ wx,
                            const float* __restrict__ wo) {
    int i = blockIdx.x * blockDim.x + threadIdx.x;
    if (i < NWH) {
        split4(((const float4*)wh)[i], g_Whh, g_Whl, (size_t)i * 4);
    } else if (i < NWH + NWX) {
        int j = i - NWH;
        split4(((const float4*)wx)[j], g_Wxh, g_Wxl, (size_t)j * 4);
    } else {
        int j = i - NWH - NWX;
        float4 v = ((const float4*)wo)[j];
        *(uint2*)(g_Wof + (size_t)j * 4) = make_uint2(cvt2h(v.x, v.y), cvt2h(v.z, v.w));
    }
}

// After xproj: S[0]=XS[0]; emit fp16 S[0] and tanh splits into T buffer 0.
__global__ void k_init_step0() {
    int i = blockIdx.x * blockDim.x + threadIdx.x;
    float4 v = *(const float4*)&g_XS[(size_t)i * 4];
    *(uint2*)(g_Sf + (size_t)i * 4) = make_uint2(cvt2h(v.x, v.y), cvt2h(v.z, v.w));
    float4 th = make_float4(tanhf(v.x), tanhf(v.y), tanhf(v.z), tanhf(v.w));
    split4(th, g_Th, g_Tl, (size_t)i * 4);
}

__global__ void k_zero_first(float* __restrict__ out) {
    int b = blockIdx.x;
    float4* p = (float4*)(out + (size_t)b * (Tq + 1) * DOUT);
    p[threadIdx.x] = make_float4(0.f, 0.f, 0.f, 0.f);
}

// ===========================================================================
// Kernel 1: XS[t] = seq_t @ Wx^T + Wx_b + Wh_b   (bf16 3-product)
// ===========================================================================
__global__ void __launch_bounds__(256) k_xproj_mm(
        const float* __restrict__ seq,
        const float* __restrict__ Wx_b, const float* __restrict__ Wh_b) {
    extern __shared__ char sb[];
    char* Ah = sb;
    char* Al = sb + TILE_B;
    char* Bh = sb + 2 * TILE_B;
    char* Bl = sb + 3 * TILE_B;
    const int t = blockIdx.y, n0 = blockIdx.x << 7;
    const int tid = threadIdx.x;
    const int w = tid >> 5, lane = tid & 31;
    const int m0 = (w & 3) * 32, nw0 = (w >> 2) * 64;
    const int qr = lane >> 2, qc2 = (lane & 3) * 2;

    float acc[2][8][4] = {};
    const float* A = seq + (size_t)t * DIN;
#pragma unroll
    for (int c = 0; c < DIN / 64; c++) {
        __syncthreads();
        conv_tile(A + c * 64, (size_t)Tq * DIN, Ah, Al, tid);
        copy64(g_Wxh + (size_t)n0 * DIN + c * 64, DIN, Bh, tid);
        copy64(g_Wxl + (size_t)n0 * DIN + c * 64, DIN, Bl, tid);
        __syncthreads();
        mma_chunk72(Ah, Al, Bh, Bl, m0, nw0, qr, qc2, acc);
    }

    float* C = g_XS + (size_t)t * STEP_ELEMS;
#pragma unroll
    for (int mi = 0; mi < 2; mi++) {
        const int r = m0 + mi * 16 + qr;
#pragma unroll
        for (int n = 0; n < 8; n++) {
            const int col = n0 + nw0 + n * 8 + qc2;
            float bv0 = Wx_b[col] + Wh_b[col];
            float bv1 = Wx_b[col + 1] + Wh_b[col + 1];
            *(float2*)(C + (size_t)r * DH + col) =
                make_float2(acc[mi][n][0] + bv0, acc[mi][n][1] + bv1);
            *(float2*)(C + (size_t)(r + 8) * DH + col) =
                make_float2(acc[mi][n][2] + bv0, acc[mi][n][3] + bv1);
        }
    }
}

// ===========================================================================
// Kernel 3: out[:, t+1, :] = S[t] @ Wo^T + Wo_b   (fp16 single-product)
// ===========================================================================
__global__ void __launch_bounds__(256) k_out_mm(
        const float* __restrict__ Wo_b, float* __restrict__ out) {
    extern __shared__ char sb[];
    char* Af = sb;
    char* Bf = sb + TILE_B;
    const int t = blockIdx.y, n0 = blockIdx.x << 7;
    const int tid = threadIdx.x;
    const int w = tid >> 5, lane = tid & 31;
    const int m0 = (w & 3) * 32, nw0 = (w >> 2) * 64;
    const int qr = lane >> 2, qc2 = (lane & 3) * 2;

    float acc[2][8][4] = {};
    const __nv_bfloat16* Sp = (const __nv_bfloat16*)(g_Sf + (size_t)t * STEP_ELEMS);
    const __nv_bfloat16* Wp = (const __nv_bfloat16*)(g_Wof + (size_t)n0 * DH);
#pragma unroll 1
    for (int c = 0; c < DH / 64; c++) {
        __syncthreads();
        copy64(Sp + c * 64, DH, Af, tid);
        copy64(Wp + c * 64, DH, Bf, tid);
        __syncthreads();
        mma_chunk72h(Af, Bf, m0, nw0, qr, qc2, acc);
    }

    float* C = out + (size_t)(t + 1) * DOUT;
    const size_t ldc = (size_t)(Tq + 1) * DOUT;
#pragma unroll
    for (int mi = 0; mi < 2; mi++) {
        const int r = m0 + mi * 16 + qr;
#pragma unroll
        for (int n = 0; n < 8; n++) {
            const int col = n0 + nw0 + n * 8 + qc2;
            float bv0 = Wo_b[col], bv1 = Wo_b[col + 1];
            *(float2*)(C + (size_t)r * ldc + col) =
                make_float2(acc[mi][n][0] + bv0, acc[mi][n][1] + bv1);
            *(float2*)(C + (size_t)(r + 8) * ldc + col) =
                make_float2(acc[mi][n][2] + bv0, acc[mi][n][3] + bv1);
        }
    }
}

// ===========================================================================
// Persistent recurrence. 128 blocks = 16 N-tiles (64 wide) x 8 K-slices (128 wide).
// Warp tile 32M x 16N; Wh B-fragments hoisted into registers (loaded once).
// Group-local flag sync; double-buffered T and P; reduce fuses tanh + splits + fp16 S.
// ===========================================================================
#define PW 136
#define PWB (PW * 2)
#define SMEM_RC (2 * (128 * PWB) + 2 * (64 * PWB))   /* 104448 */

__device__ __forceinline__ void grid_sync(unsigned& sense, unsigned nb) {
    __threadfence();
    __syncthreads();
    sense ^= 1u;
    if (threadIdx.x == 0) {
        unsigned prev = atomicAdd(&g_bar_count, 1u);
        if (prev == nb - 1u) {
            atomicExch(&g_bar_count, 0u);
            __threadfence();
            atomicExch(&g_bar_sense, sense);
        } else {
            unsigned v;
            do {
                asm volatile("ld.acquire.gpu.b32 %0, [%1];" : "=r"(v) : "l"(&g_bar_sense));
            } while (v != sense);
        }
    }
    __syncthreads();
}

__global__ void __launch_bounds__(512, 1) k_recur() {
    extern __shared__ char sb[];
    char* Ah = sb;                          // 128 x 136 bf16 = 34816
    char* Al = sb + 34816;
    char* Bh = sb + 2 * 34816;              // 64 x 136 bf16 = 17408
    char* Bl = sb + 2 * 34816 + 17408;

    const int tid = threadIdx.x;
    const int w = tid >> 5, lane = tid & 31;
    const int mg = w & 3;                   // M group of 32 rows
    const int ng = w >> 2;                  // N group of 16 cols
    const int qr = lane >> 2, qc2 = (lane & 3) * 2;

    const int ns = blockIdx.x >> 3;         // 0..15  N tile (64 wide)
    const int ks = blockIdx.x & 7;          // 0..7   K slice (128 wide)
    const int n0 = ns << 6;
    const int kbase = ks << 7;
    const unsigned nb = gridDim.x;

    unsigned sense;
    asm volatile("ld.acquire.gpu.b32 %0, [%1];" : "=r"(sense) : "l"(&g_bar_sense));

    // Reset flags (replay-safe), then one full barrier.
    if (blockIdx.x == 0 && tid == 0) {
#pragma unroll
        for (int i = 0; i < 16; i++) g_fA[i] = 0u;
#pragma unroll
        for (int i = 0; i < 8; i++) { g_fB[i] = 0u; g_fC[i] = 0u; }
    }

    // Wh slice -> smem (once)
#pragma unroll
    for (int i = 0; i < 2; i++) {
        int f = i * 512 + tid;
        int row = f >> 4, c = f & 15;
        *(uint4*)(Bh + row * PWB + c * 16) =
            *(const uint4*)(g_Whh + (size_t)(n0 + row) * DH + kbase + c * 8);
        *(uint4*)(Bl + row * PWB + c * 16) =
            *(const uint4*)(g_Whl + (size_t)(n0 + row) * DH + kbase + c * 8);
    }
    __syncthreads();

    // Hoist this warp's B fragments into registers (persistent across all steps)
    uint32_t Bfh[8][2][2], Bfl[8][2][2];
#pragma unroll
    for (int k16 = 0; k16 < 8; k16++) {
        const int k0 = k16 * 16;
#pragma unroll
        for (int n = 0; n < 2; n++) {
            const int rn = 16 * ng + n * 8 + qr;
            Bfh[k16][n][0] = ldsw<68>(Bh, rn, k0 + qc2);
            Bfh[k16][n][1] = ldsw<68>(Bh, rn, k0 + qc2 + 8);
            Bfl[k16][n][0] = ldsw<68>(Bl, rn, k0 + qc2);
            Bfl[k16][n][1] = ldsw<68>(Bl, rn, k0 + qc2 + 8);
        }
    }
    grid_sync(sense, nb);

    float* const Pb0 = g_P + (size_t)blockIdx.x * 8192;

    for (int t = 1; t < Tq; t++) {
        const unsigned ut = (unsigned)t;
        const unsigned tm1 = ut - 1u;
        // gate 1 (parallel polls): A data ready + P buffer anti-dep
        if (lane == 0) {
            if (w == 0) waitge(&g_fB[ks], 16u * tm1);
            else if (w == 1) waitge(&g_fB[ns >> 1], 16u * tm1);
        }
        __syncthreads();

        // phase A: copy tanh splits (buffer (t-1)&1) into smem
        const __nv_bfloat16* Thp = g_Th + (size_t)((t - 1) & 1) * STEP_ELEMS;
        const __nv_bfloat16* Tlp = g_Tl + (size_t)((t - 1) & 1) * STEP_ELEMS;
#pragma unroll
        for (int i = 0; i < 4; i++) {
            int f = i * 512 + tid;
            int row = f >> 4, c = f & 15;
            *(uint4*)(Ah + row * PWB + c * 16) =
                *(const uint4*)(Thp + (size_t)row * DH + kbase + c * 8);
            *(uint4*)(Al + row * PWB + c * 16) =
                *(const uint4*)(Tlp + (size_t)row * DH + kbase + c * 8);
        }
        __syncthreads();
        if (tid == 0) redrel(&g_fC[ks]);    // done reading T slice

        // MMA: warp tile 32M x 16N over K=128, B fragments in registers
        float acc[2][2][4] = {};
#pragma unroll
        for (int k16 = 0; k16 < 8; k16++) {
            const int k0 = k16 * 16;
            uint32_t ah[2][4], al[2][4];
#pragma unroll
            for (int mi = 0; mi < 2; mi++) {
                const int r = 32 * mg + 16 * mi + qr;
                ah[mi][0] = ldsw<68>(Ah, r,     k0 + qc2);
                ah[mi][1] = ldsw<68>(Ah, r + 8, k0 + qc2);
                ah[mi][2] = ldsw<68>(Ah, r,     k0 + qc2 + 8);
                ah[mi][3] = ldsw<68>(Ah, r + 8, k0 + qc2 + 8);
                al[mi][0] = ldsw<68>(Al, r,     k0 + qc2);
                al[mi][1] = ldsw<68>(Al, r + 8, k0 + qc2);
                al[mi][2] = ldsw<68>(Al, r,     k0 + qc2 + 8);
                al[mi][3] = ldsw<68>(Al, r + 8, k0 + qc2 + 8);
            }
#pragma unroll
            for (int mi = 0; mi < 2; mi++)
#pragma unroll
                for (int n = 0; n < 2; n++) {
                    mma16816(acc[mi][n], ah[mi], Bfh[k16][n]);
                    mma16816(acc[mi][n], ah[mi], Bfl[k16][n]);
                    mma16816(acc[mi][n], al[mi], Bfh[k16][n]);
                }
        }

        // write partial [128 x 64] fp32 to P buffer t&1
        float* Pmine = Pb0 + (size_t)(t & 1) * 128 * 8192;
#pragma unroll
        for (int mi = 0; mi < 2; mi++) {
            const int r = 32 * mg + 16 * mi + qr;
#pragma unroll
            for (int n = 0; n < 2; n++) {
                const int col = 16 * ng + 8 * n + qc2;
                *(float2*)&Pmine[r * 64 + col]       = make_float2(acc[mi][n][0], acc[mi][n][1]);
                *(float2*)&Pmine[(r + 8) * 64 + col] = make_float2(acc[mi][n][2], acc[mi][n][3]);
            }
        }
        __syncthreads();
        if (tid == 0) redrel(&g_fA[ns]);

        // gate 2 (parallel polls): producers of our reduce patch + T WAR guard
        if (lane == 0) {
            if (w == 0) waitge(&g_fA[2 * ks],     8u * ut);
            else if (w == 1) waitge(&g_fA[2 * ks + 1], 8u * ut);
            else if (w == 2) waitge(&g_fC[ks], 16u * tm1);
        }
        __syncthreads();

        // reduce: rows [8ns,+8), cols [128ks,+128); fuse tanh + splits + fp16 S
        {
            const int m = 8 * ns + (tid >> 6);
            const int c = 128 * ks + (tid & 63) * 2;
            const float* Pbase = g_P + (size_t)(t & 1) * 128 * 8192;
            float2 s = *(const float2*)&g_XS[(size_t)t * STEP_ELEMS + m * DH + c];
            const float* Pp = Pbase + (size_t)((2 * ks + ((tid & 63) >> 5)) * 8) * 8192
                              + m * 64 + (c & 63);
#pragma unroll
            for (int q = 0; q < 8; q++) {
                float2 p = *(const float2*)&Pp[(size_t)q * 8192];
                s.x += p.x; s.y += p.y;
            }
            const size_t se = (size_t)t * STEP_ELEMS + m * DH + c;
            *(uint32_t*)((char*)g_Sf + se * 2) = cvt2h(s.x, s.y);
            float t0 = tanhf(s.x), t1 = tanhf(s.y);
            uint32_t th01 = cvt2bf(t0, t1);
            float tl0 = t0 - __uint_as_float(th01 << 16);
            float tl1 = t1 - __uint_as_float(th01 & 0xFFFF0000u);
            const size_t te = (size_t)(t & 1) * STEP_ELEMS + m * DH + c;
            *(uint32_t*)((char*)g_Th + te * 2) = th01;
            *(uint32_t*)((char*)g_Tl + te * 2) = cvt2bf(tl0, tl1);
        }
        __syncthreads();
        if (tid == 0) redrel(&g_fB[ks]);
    }
}

// ===========================================================================
extern "C" void kernel_launch(void* const* d_in, const int* in_sizes, int n_in,
                              void* d_out, int out_size) {
    const float* seq  = (const float*)d_in[0];
    const float* Wh_w = (const float*)d_in[1];
    const float* Wh_b = (const float*)d_in[2];
    const float* Wx_w = (const float*)d_in[3];
    const float* Wx_b = (const float*)d_in[4];
    const float* Wo_w = (const float*)d_in[5];
    const float* Wo_b = (const float*)d_in[6];
    float* out = (float*)d_out;

    cudaFuncSetAttribute(k_xproj_mm, cudaFuncAttributeMaxDynamicSharedMemorySize, SMEM72);
    cudaFuncSetAttribute(k_out_mm,   cudaFuncAttributeMaxDynamicSharedMemorySize, SMEM_OUT);
    cudaFuncSetAttribute(k_recur,    cudaFuncAttributeMaxDynamicSharedMemorySize, SMEM_RC);

    k_split_all<<<(NWH + NWX + NWO) / 256, 256>>>(Wh_w, Wx_w, Wo_w);
    k_zero_first<<<Bq, 256>>>(out);
    dim3 gp(DH / 128, Tq);
    k_xproj_mm<<<gp, 256, SMEM72>>>(seq, Wx_b, Wh_b);
    k_init_step0<<<128, 256>>>();
    k_recur<<<128, 512, SMEM_RC>>>();
    dim3 go(DOUT / 128, Tq);
    k_out_mm<<<go, 256, SMEM_OUT>>>(Wo_b, out);
}